// round 2
// baseline (speedup 1.0000x reference)
#include <cuda_runtime.h>
#include <math.h>

// Problem constants
#define Hd   512
#define G4   2048      // 4*H
#define Ed   250
#define Bd   32
#define NCd  5
#define Td   20
#define Rd   160       // NC*B
#define Vd   30522
#define CNNd 2048
#define Md   3200      // NC*T*B

// ---------------- device scratch (no allocations allowed) ----------------
// Packed weights: B-matrix layout [K][N], N interleaved as n = h*4 + gate
__device__ float g_WihP0[2][Ed][G4];
__device__ float g_WhhP0[2][Hd][G4];
__device__ float g_WihP1[2][2 * Hd][G4];
__device__ float g_WhhP1[2][Hd][G4];
__device__ float g_bP0[2][G4];
__device__ float g_bP1[2][G4];
// Precomputed layer0 input projections (prefix-invariant): [dir][t][row][n]
__device__ float g_X0[2][Td][Rd][G4];
// Per-w layer1 input projections: [dir][t][row][n]
__device__ float g_Z[2][Td][Rd][G4];
// LSTM h state, double buffered: [parity][layer][dir][row][h]
__device__ float g_hbuf[2][2][2][Rd][Hd];
// LSTM c state (in-place safe): [layer][dir][row][h]
__device__ float g_cS[2][2][Rd][Hd];
// layer0 output sequences (scan order): [dir][s][row][h]
__device__ float g_hs[2][Td][Rd][Hd];
// packed final states for vocab projection: [m][2H]
__device__ float g_packed[Md][2 * Hd];

// ---------------- weight packing ----------------
__global__ void k_pack(const float* __restrict__ Wih0, const float* __restrict__ Whh0,
                       const float* __restrict__ bih0, const float* __restrict__ bhh0,
                       const float* __restrict__ Wih1, const float* __restrict__ Whh1,
                       const float* __restrict__ bih1, const float* __restrict__ bhh1) {
    int region = blockIdx.y;
    long i = (long)blockIdx.x * blockDim.x + threadIdx.x;
    if (region == 0) {                       // WihP0: [2][250][2048]
        if (i >= 2L * Ed * G4) return;
        int d = (int)(i / (Ed * G4)); int rem = (int)(i % (Ed * G4));
        int k = rem / G4, n = rem % G4;
        int h = n >> 2, g = n & 3;
        g_WihP0[d][k][n] = Wih0[((long)d * G4 + g * Hd + h) * Ed + k];
    } else if (region == 1) {                // WhhP0: [2][512][2048]
        if (i >= 2L * Hd * G4) return;
        int d = (int)(i / (Hd * G4)); int rem = (int)(i % (Hd * G4));
        int k = rem / G4, n = rem % G4;
        int h = n >> 2, g = n & 3;
        g_WhhP0[d][k][n] = Whh0[((long)d * G4 + g * Hd + h) * Hd + k];
    } else if (region == 2) {                // WihP1: [2][1024][2048]
        if (i >= 2L * 2 * Hd * G4) return;
        int d = (int)(i / (2 * Hd * G4)); int rem = (int)(i % (2 * Hd * G4));
        int k = rem / G4, n = rem % G4;
        int h = n >> 2, g = n & 3;
        g_WihP1[d][k][n] = Wih1[((long)d * G4 + g * Hd + h) * (2 * Hd) + k];
    } else if (region == 3) {                // WhhP1: [2][512][2048]
        if (i >= 2L * Hd * G4) return;
        int d = (int)(i / (Hd * G4)); int rem = (int)(i % (Hd * G4));
        int k = rem / G4, n = rem % G4;
        int h = n >> 2, g = n & 3;
        g_WhhP1[d][k][n] = Whh1[((long)d * G4 + g * Hd + h) * Hd + k];
    } else if (region == 4) {                // bP0
        if (i >= 2L * G4) return;
        int d = (int)(i / G4); int n = (int)(i % G4);
        int h = n >> 2, g = n & 3;
        long j = (long)d * G4 + g * Hd + h;
        g_bP0[d][n] = bih0[j] + bhh0[j];
    } else {                                 // bP1
        if (i >= 2L * G4) return;
        int d = (int)(i / G4); int n = (int)(i % G4);
        int h = n >> 2, g = n & 3;
        long j = (long)d * G4 + g * Hd + h;
        g_bP1[d][n] = bih1[j] + bhh1[j];
    }
}

// ---------------- initial states: h0/c0 = relu(img @ W.T + b), broadcast ----------------
__global__ void k_init(const float* __restrict__ img, const float* __restrict__ Wh,
                       const float* __restrict__ bh, const float* __restrict__ Wc,
                       const float* __restrict__ bc) {
    int i = blockIdx.x * blockDim.x + threadIdx.x;    // 2 * 32 * 512
    if (i >= 2 * Bd * Hd) return;
    int which = i / (Bd * Hd);
    int rem = i % (Bd * Hd);
    int b = rem / Hd, j = rem % Hd;
    const float* W = which ? Wc : Wh;
    const float* bias = which ? bc : bh;
    const float4* a4 = (const float4*)(img + (long)b * CNNd);
    const float4* w4 = (const float4*)(W + (long)j * CNNd);
    float acc = 0.f;
#pragma unroll 4
    for (int k = 0; k < CNNd / 4; k++) {
        float4 a = a4[k], w = w4[k];
        acc += a.x * w.x + a.y * w.y + a.z * w.z + a.w * w.w;
    }
    float v = fmaxf(acc + bias[j], 0.f);
    for (int nc = 0; nc < NCd; nc++) {
        int row = nc * Bd + b;
        for (int l = 0; l < 2; l++)
            for (int d = 0; d < 2; d++) {
                if (which == 0) g_hbuf[0][l][d][row][j] = v;
                else            g_cS[l][d][row][j] = v;
            }
    }
}

// ---------------- layer0 input projections for all t (prefix-invariant) ----------------
// grid (100, 16, 2), block 256. C[m][n] = emb[tok(m)] @ WihP0[d] + bP0[d]
__global__ void k_xproj(const float* __restrict__ emb, const int* __restrict__ cap) {
    __shared__ float xs[32 * Ed];
    __shared__ int toks[32];
    int bm = blockIdx.x, bn = blockIdx.y, d = blockIdx.z;
    int tid = threadIdx.x;
    if (tid < 32) {
        int m = bm * 32 + tid;
        int t = m / Rd, r = m % Rd;
        int nc = r >> 5, b = r & 31;
        toks[tid] = cap[b * (NCd * Td) + nc * Td + t];
    }
    __syncthreads();
    for (int e = tid; e < 32 * Ed; e += 256) {
        int lr = e / Ed, k = e % Ed;
        xs[e] = emb[(long)toks[lr] * Ed + k];
    }
    __syncthreads();
    int tx = tid & 31, ty = tid >> 5;     // rows: ty + jr*8 ; cols: tx + jc*32
    float acc[4][4];
#pragma unroll
    for (int a = 0; a < 4; a++)
#pragma unroll
        for (int c = 0; c < 4; c++) acc[a][c] = 0.f;
    int n0 = bn * 128;
    const float* Bp = &g_WihP0[d][0][0];
#pragma unroll 2
    for (int k = 0; k < Ed; k++) {
        float av[4], bv[4];
#pragma unroll
        for (int jr = 0; jr < 4; jr++) av[jr] = xs[(ty + jr * 8) * Ed + k];
#pragma unroll
        for (int jc = 0; jc < 4; jc++) bv[jc] = Bp[(long)k * G4 + n0 + tx + jc * 32];
#pragma unroll
        for (int jr = 0; jr < 4; jr++)
#pragma unroll
            for (int jc = 0; jc < 4; jc++) acc[jr][jc] += av[jr] * bv[jc];
    }
    int m0 = bm * 32;
#pragma unroll
    for (int jr = 0; jr < 4; jr++) {
        int m = m0 + ty + jr * 8;
        int t = m / Rd, r = m % Rd;
#pragma unroll
        for (int jc = 0; jc < 4; jc++) {
            int n = n0 + tx + jc * 32;
            g_X0[d][t][r][n] = acc[jr][jc] + g_bP0[d][n];
        }
    }
}

// ---------------- layer1 input projections for word w ----------------
// grid ((w+1)*5, 16, 2), block 256.  A = Y[t] = [hsf[t], hsb_scan[w-t]]
__global__ void k_zproj(int w) {
    __shared__ float As[32 * 33];
    int bm = blockIdx.x, bn = blockIdx.y, d = blockIdx.z;
    int tid = threadIdx.x;
    int m0 = bm * 32;
    int t = m0 / Rd;          // tile-constant (32 | 160)
    int r0 = m0 % Rd;
    int tb = w - t;
    int tx = tid & 31, ty = tid >> 5;
    float acc[4][4];
#pragma unroll
    for (int a = 0; a < 4; a++)
#pragma unroll
        for (int c = 0; c < 4; c++) acc[a][c] = 0.f;
    int n0 = bn * 128;
    const float* Bp = &g_WihP1[d][0][0];
    for (int kb = 0; kb < 2 * Hd; kb += 32) {
        __syncthreads();
        for (int e = tid; e < 1024; e += 256) {
            int lr = e >> 5, kk = e & 31;
            int k = kb + kk;
            float v = (k < Hd) ? g_hs[0][t][r0 + lr][k]
                               : g_hs[1][tb][r0 + lr][k - Hd];
            As[lr * 33 + kk] = v;
        }
        __syncthreads();
#pragma unroll 4
        for (int kk = 0; kk < 32; kk++) {
            float av[4], bv[4];
#pragma unroll
            for (int jr = 0; jr < 4; jr++) av[jr] = As[(ty + jr * 8) * 33 + kk];
#pragma unroll
            for (int jc = 0; jc < 4; jc++)
                bv[jc] = Bp[(long)(kb + kk) * G4 + n0 + tx + jc * 32];
#pragma unroll
            for (int jr = 0; jr < 4; jr++)
#pragma unroll
                for (int jc = 0; jc < 4; jc++) acc[jr][jc] += av[jr] * bv[jc];
        }
    }
#pragma unroll
    for (int jr = 0; jr < 4; jr++) {
        int r = r0 + ty + jr * 8;
#pragma unroll
        for (int jc = 0; jc < 4; jc++) {
            int n = n0 + tx + jc * 32;
            g_Z[d][t][r][n] = acc[jr][jc] + g_bP1[d][n];
        }
    }
}

// ---------------- one LSTM recurrent step (both dirs via grid.z), fused cell ----------------
// grid (5, 32, 2), block 256. gates = Xpre + h_in @ WhhP ; update c,h.
__global__ void k_step(int l, int p, int s, int w) {
    __shared__ float As[32 * 128];
    int bm = blockIdx.x, bn = blockIdx.y, d = blockIdx.z;
    int tid = threadIdx.x;
    int r0 = bm * 32;
    const float (*hin)[Hd] = g_hbuf[p][l][d];
    float (*hout)[Hd] = g_hbuf[p ^ 1][l][d];
    float (*cst)[Hd] = g_cS[l][d];
    const float* Wp = l ? &g_WhhP1[d][0][0] : &g_WhhP0[d][0][0];
    int xidx = d ? (w - s) : s;
    const float* Xp = l ? &g_Z[d][xidx][0][0] : &g_X0[d][xidx][0][0];

    int tx = tid & 15, ty = tid >> 4;          // cols: 4 consecutive (one h-unit)
    int n0 = bn * 64 + tx * 4;
    float acc[2][4];
#pragma unroll
    for (int a = 0; a < 2; a++)
#pragma unroll
        for (int c = 0; c < 4; c++) acc[a][c] = 0.f;

    for (int kb = 0; kb < Hd; kb += 128) {
        __syncthreads();
        for (int e = tid * 4; e < 32 * 128; e += 256 * 4) {
            int lr = e >> 7, k = e & 127;
            *(float4*)&As[e] = *(const float4*)&hin[r0 + lr][kb + k];
        }
        __syncthreads();
#pragma unroll 8
        for (int kk = 0; kk < 128; kk++) {
            float4 bv = *(const float4*)&Wp[(long)(kb + kk) * G4 + n0];
            float a0 = As[ty * 128 + kk];
            float a1 = As[(ty + 16) * 128 + kk];
            acc[0][0] += a0 * bv.x; acc[0][1] += a0 * bv.y;
            acc[0][2] += a0 * bv.z; acc[0][3] += a0 * bv.w;
            acc[1][0] += a1 * bv.x; acc[1][1] += a1 * bv.y;
            acc[1][2] += a1 * bv.z; acc[1][3] += a1 * bv.w;
        }
    }
    int hh = n0 >> 2;
#pragma unroll
    for (int jr = 0; jr < 2; jr++) {
        int row = r0 + ty + jr * 16;
        float4 xr = *(const float4*)(Xp + (long)row * G4 + n0);
        float gi = acc[jr][0] + xr.x;
        float gf = acc[jr][1] + xr.y;
        float gg = acc[jr][2] + xr.z;
        float go = acc[jr][3] + xr.w;
        float si = 1.f / (1.f + expf(-gi));
        float sf = 1.f / (1.f + expf(-gf));
        float so = 1.f / (1.f + expf(-go));
        float tg = tanhf(gg);
        float c = sf * cst[row][hh] + si * tg;
        float h = so * tanhf(c);
        cst[row][hh] = c;
        hout[row][hh] = h;
        if (l == 0) g_hs[d][s][row][hh] = h;
    }
}

// ---------------- pack final layer1 states for word w: [bwd_h, fwd_h] ----------------
__global__ void k_packst(int w, int pb) {
    int i = blockIdx.x * blockDim.x + threadIdx.x;
    if (i >= Rd * 2 * Hd) return;
    int r = i / (2 * Hd), k = i % (2 * Hd);
    int nc = r >> 5, b = r & 31;
    float v = (k < Hd) ? g_hbuf[pb][1][1][r][k]       // layer1 backward final h
                       : g_hbuf[pb][1][0][r][k - Hd]; // layer1 forward final h
    g_packed[(nc * Td + w) * Bd + b][k] = v;
}

// ---------------- final vocab projection: out = packed @ Wfc.T + bfc ----------------
// grid (100, 239), block 256
__global__ void k_final(const float* __restrict__ Wfc, const float* __restrict__ bfc,
                        float* __restrict__ out) {
    __shared__ float As[32 * 33];
    __shared__ float Ws[128 * 33];
    int bm = blockIdx.x, bn = blockIdx.y;
    int tid = threadIdx.x;
    int m0 = bm * 32, n0 = bn * 128;
    int tx = tid & 31, ty = tid >> 5;
    float acc[4][4];
#pragma unroll
    for (int a = 0; a < 4; a++)
#pragma unroll
        for (int c = 0; c < 4; c++) acc[a][c] = 0.f;
    for (int kb = 0; kb < 2 * Hd; kb += 32) {
        __syncthreads();
        for (int e = tid; e < 1024; e += 256) {
            int lr = e >> 5, kk = e & 31;
            As[lr * 33 + kk] = g_packed[m0 + lr][kb + kk];
        }
        for (int e = tid; e < 4096; e += 256) {
            int nn = e >> 5, kk = e & 31;
            int n = n0 + nn;
            Ws[nn * 33 + kk] = (n < Vd) ? Wfc[(long)n * (2 * Hd) + kb + kk] : 0.f;
        }
        __syncthreads();
#pragma unroll 4
        for (int kk = 0; kk < 32; kk++) {
            float av[4], bv[4];
#pragma unroll
            for (int jr = 0; jr < 4; jr++) av[jr] = As[(ty + jr * 8) * 33 + kk];
#pragma unroll
            for (int jc = 0; jc < 4; jc++) bv[jc] = Ws[(tx + jc * 32) * 33 + kk];
#pragma unroll
            for (int jr = 0; jr < 4; jr++)
#pragma unroll
                for (int jc = 0; jc < 4; jc++) acc[jr][jc] += av[jr] * bv[jc];
        }
    }
#pragma unroll
    for (int jr = 0; jr < 4; jr++) {
        int m = m0 + ty + jr * 8;
#pragma unroll
        for (int jc = 0; jc < 4; jc++) {
            int n = n0 + tx + jc * 32;
            if (n < Vd) out[(long)m * Vd + n] = acc[jr][jc] + bfc[n];
        }
    }
}

// ---------------- host orchestration (graph-capturable: launches only) ----------------
extern "C" void kernel_launch(void* const* d_in, const int* in_sizes, int n_in,
                              void* d_out, int out_size) {
    const float* img  = (const float*)d_in[0];
    const int*   cap  = (const int*)d_in[1];
    const float* emb  = (const float*)d_in[2];
    const float* Wh   = (const float*)d_in[3];
    const float* bh   = (const float*)d_in[4];
    const float* Wc   = (const float*)d_in[5];
    const float* bc   = (const float*)d_in[6];
    const float* Wih0 = (const float*)d_in[7];
    const float* Whh0 = (const float*)d_in[8];
    const float* bih0 = (const float*)d_in[9];
    const float* bhh0 = (const float*)d_in[10];
    const float* Wih1 = (const float*)d_in[11];
    const float* Whh1 = (const float*)d_in[12];
    const float* bih1 = (const float*)d_in[13];
    const float* bhh1 = (const float*)d_in[14];
    const float* Wfc  = (const float*)d_in[15];
    const float* bfc  = (const float*)d_in[16];
    float* out = (float*)d_out;

    k_pack<<<dim3(16384, 6), 256>>>(Wih0, Whh0, bih0, bhh0, Wih1, Whh1, bih1, bhh1);
    k_init<<<(2 * Bd * Hd + 255) / 256, 256>>>(img, Wh, bh, Wc, bc);
    k_xproj<<<dim3(100, 16, 2), 256>>>(emb, cap);

    int p0 = 0, p1 = 0;
    for (int w = 0; w < Td; w++) {
        for (int s = 0; s <= w; s++) {
            k_step<<<dim3(5, 32, 2), 256>>>(0, p0, s, w);
            p0 ^= 1;
        }
        k_zproj<<<dim3((w + 1) * 5, 16, 2), 256>>>(w);
        for (int s = 0; s <= w; s++) {
            k_step<<<dim3(5, 32, 2), 256>>>(1, p1, s, w);
            p1 ^= 1;
        }
        k_packst<<<(Rd * 2 * Hd + 255) / 256, 256>>>(w, p1);
    }
    k_final<<<dim3(100, 239), 256>>>(Wfc, bfc, out);
}

// round 3
// speedup vs baseline: 2.0912x; 2.0912x over previous
#include <cuda_runtime.h>
#include <math.h>

// Problem constants
#define Hd   512
#define G4   2048      // 4*H
#define Ed   250
#define Bd   32
#define NCd  5
#define Td   20
#define Rd   160       // NC*B
#define Vd   30522
#define CNNd 2048
#define Md   3200      // NC*T*B

// ---------------- device scratch (no allocations allowed) ----------------
__device__ float g_WihP0[2][Ed][G4];
__device__ float g_WhhP0[2][Hd][G4];
__device__ float g_WihP1[2][2 * Hd][G4];
__device__ float g_WhhP1[2][Hd][G4];
__device__ float g_bP0[2][G4];
__device__ float g_bP1[2][G4];
__device__ float g_X0[2][Td][Rd][G4];        // layer0 input projections (+bias)
__device__ float g_Z[2][Td][Rd][G4];         // layer1 input projections (+bias)
__device__ float g_hbuf[2][2][2][Rd][Hd];    // [parity][layer][dir][row][h]
__device__ float g_cS[2][2][Rd][Hd];         // [layer][dir][row][h]
__device__ float g_hs[2][Td][Rd][Hd];        // layer0 outputs, scan order
__device__ float g_packed[Md][2 * Hd];

// ---------------- weight packing ----------------
__global__ void k_pack(const float* __restrict__ Wih0, const float* __restrict__ Whh0,
                       const float* __restrict__ bih0, const float* __restrict__ bhh0,
                       const float* __restrict__ Wih1, const float* __restrict__ Whh1,
                       const float* __restrict__ bih1, const float* __restrict__ bhh1) {
    int region = blockIdx.y;
    long i = (long)blockIdx.x * blockDim.x + threadIdx.x;
    if (region == 0) {
        if (i >= 2L * Ed * G4) return;
        int d = (int)(i / (Ed * G4)); int rem = (int)(i % (Ed * G4));
        int k = rem / G4, n = rem % G4;
        int h = n >> 2, g = n & 3;
        g_WihP0[d][k][n] = Wih0[((long)d * G4 + g * Hd + h) * Ed + k];
    } else if (region == 1) {
        if (i >= 2L * Hd * G4) return;
        int d = (int)(i / (Hd * G4)); int rem = (int)(i % (Hd * G4));
        int k = rem / G4, n = rem % G4;
        int h = n >> 2, g = n & 3;
        g_WhhP0[d][k][n] = Whh0[((long)d * G4 + g * Hd + h) * Hd + k];
    } else if (region == 2) {
        if (i >= 2L * 2 * Hd * G4) return;
        int d = (int)(i / (2 * Hd * G4)); int rem = (int)(i % (2 * Hd * G4));
        int k = rem / G4, n = rem % G4;
        int h = n >> 2, g = n & 3;
        g_WihP1[d][k][n] = Wih1[((long)d * G4 + g * Hd + h) * (2 * Hd) + k];
    } else if (region == 3) {
        if (i >= 2L * Hd * G4) return;
        int d = (int)(i / (Hd * G4)); int rem = (int)(i % (Hd * G4));
        int k = rem / G4, n = rem % G4;
        int h = n >> 2, g = n & 3;
        g_WhhP1[d][k][n] = Whh1[((long)d * G4 + g * Hd + h) * Hd + k];
    } else if (region == 4) {
        if (i >= 2L * G4) return;
        int d = (int)(i / G4); int n = (int)(i % G4);
        int h = n >> 2, g = n & 3;
        long j = (long)d * G4 + g * Hd + h;
        g_bP0[d][n] = bih0[j] + bhh0[j];
    } else {
        if (i >= 2L * G4) return;
        int d = (int)(i / G4); int n = (int)(i % G4);
        int h = n >> 2, g = n & 3;
        long j = (long)d * G4 + g * Hd + h;
        g_bP1[d][n] = bih1[j] + bhh1[j];
    }
}

// ---------------- initial states ----------------
__global__ void k_init(const float* __restrict__ img, const float* __restrict__ Wh,
                       const float* __restrict__ bh, const float* __restrict__ Wc,
                       const float* __restrict__ bc) {
    int i = blockIdx.x * blockDim.x + threadIdx.x;
    if (i >= 2 * Bd * Hd) return;
    int which = i / (Bd * Hd);
    int rem = i % (Bd * Hd);
    int b = rem / Hd, j = rem % Hd;
    const float* W = which ? Wc : Wh;
    const float* bias = which ? bc : bh;
    const float4* a4 = (const float4*)(img + (long)b * CNNd);
    const float4* w4 = (const float4*)(W + (long)j * CNNd);
    float acc = 0.f;
#pragma unroll 4
    for (int k = 0; k < CNNd / 4; k++) {
        float4 a = a4[k], w = w4[k];
        acc += a.x * w.x + a.y * w.y + a.z * w.z + a.w * w.w;
    }
    float v = fmaxf(acc + bias[j], 0.f);
    for (int nc = 0; nc < NCd; nc++) {
        int row = nc * Bd + b;
        for (int l = 0; l < 2; l++)
            for (int d = 0; d < 2; d++) {
                if (which == 0) g_hbuf[0][l][d][row][j] = v;
                else            g_cS[l][d][row][j] = v;
            }
    }
}

// ---------------- layer0 input projections for all t ----------------
__global__ void k_xproj(const float* __restrict__ emb, const int* __restrict__ cap) {
    __shared__ float xs[32 * Ed];
    __shared__ int toks[32];
    int bm = blockIdx.x, bn = blockIdx.y, d = blockIdx.z;
    int tid = threadIdx.x;
    if (tid < 32) {
        int m = bm * 32 + tid;
        int t = m / Rd, r = m % Rd;
        int nc = r >> 5, b = r & 31;
        toks[tid] = cap[b * (NCd * Td) + nc * Td + t];
    }
    __syncthreads();
    for (int e = tid; e < 32 * Ed; e += 256) {
        int lr = e / Ed, k = e % Ed;
        xs[e] = emb[(long)toks[lr] * Ed + k];
    }
    __syncthreads();
    int tx = tid & 31, ty = tid >> 5;
    float acc[4][4];
#pragma unroll
    for (int a = 0; a < 4; a++)
#pragma unroll
        for (int c = 0; c < 4; c++) acc[a][c] = 0.f;
    int n0 = bn * 128;
    const float* Bp = &g_WihP0[d][0][0];
#pragma unroll 5
    for (int k = 0; k < Ed; k++) {
        float av[4], bv[4];
#pragma unroll
        for (int jr = 0; jr < 4; jr++) av[jr] = xs[(ty + jr * 8) * Ed + k];
#pragma unroll
        for (int jc = 0; jc < 4; jc++) bv[jc] = Bp[(long)k * G4 + n0 + tx + jc * 32];
#pragma unroll
        for (int jr = 0; jr < 4; jr++)
#pragma unroll
            for (int jc = 0; jc < 4; jc++) acc[jr][jc] += av[jr] * bv[jc];
    }
    int m0 = bm * 32;
#pragma unroll
    for (int jr = 0; jr < 4; jr++) {
        int m = m0 + ty + jr * 8;
        int t = m / Rd, r = m % Rd;
#pragma unroll
        for (int jc = 0; jc < 4; jc++) {
            int n = n0 + tx + jc * 32;
            g_X0[d][t][r][n] = acc[jr][jc] + g_bP0[d][n];
        }
    }
}

// =========================================================================
// Combined pipelined LSTM step: layer0(word w0, step s0) and layer1(word w1,
// step s1) in one launch. Double-buffered smem GEMM 32x128, K=512.
// grid (5, 16, 4) — blockIdx.z = dir + 2*lay. block 256.
// =========================================================================
__global__ void __launch_bounds__(256)
k_step2(int p0, int s0, int w0, int act0, int p1, int s1, int w1, int act1) {
    __shared__ float As[2][32 * 36];     // [buf][row*36 + kk]
    __shared__ float Ws[2][32 * 128];    // [buf][kk*128 + col]

    int z = blockIdx.z;
    int lay = z >> 1, d = z & 1;
    int act = lay ? act1 : act0;
    if (!act) return;
    int p = lay ? p1 : p0;
    int s = lay ? s1 : s0;
    int w = lay ? w1 : w0;

    int bm = blockIdx.x, bn = blockIdx.y;
    int tid = threadIdx.x;
    int r0 = bm * 32;
    int n0c = bn * 128;

    const float* hinp = &g_hbuf[p][lay][d][0][0];
    float* houtp = &g_hbuf[p ^ 1][lay][d][0][0];
    float* cstp = &g_cS[lay][d][0][0];
    const float* Wp = lay ? &g_WhhP1[d][0][0] : &g_WhhP0[d][0][0];
    int xidx = d ? (w - s) : s;
    const float* Xp = lay ? &g_Z[d][xidx][0][0] : &g_X0[d][xidx][0][0];

    int tx = tid & 31, ty = tid >> 5;
    // staging indices
    int arow = tid >> 3, ak = (tid & 7) * 4;          // A: 32x32 tile
    int wrow = tid >> 5, wc = (tid & 31) * 4;         // W: 32x128 tile (4 rows/thread)

    float acc[4][4];
#pragma unroll
    for (int a = 0; a < 4; a++)
#pragma unroll
        for (int c = 0; c < 4; c++) acc[a][c] = 0.f;

    float4 areg, wreg[4];
    // prologue: tile 0
    areg = *(const float4*)&hinp[(r0 + arow) * Hd + ak];
#pragma unroll
    for (int j = 0; j < 4; j++)
        wreg[j] = *(const float4*)&Wp[(long)(wrow + j * 8) * G4 + n0c + wc];
    *(float4*)&As[0][arow * 36 + ak] = areg;
#pragma unroll
    for (int j = 0; j < 4; j++)
        *(float4*)&Ws[0][(wrow + j * 8) * 128 + wc] = wreg[j];

    for (int kt = 0; kt < 16; kt++) {
        __syncthreads();
        int buf = kt & 1;
        if (kt < 15) {
            int kb = (kt + 1) * 32;
            areg = *(const float4*)&hinp[(r0 + arow) * Hd + kb + ak];
#pragma unroll
            for (int j = 0; j < 4; j++)
                wreg[j] = *(const float4*)&Wp[(long)(kb + wrow + j * 8) * G4 + n0c + wc];
        }
#pragma unroll 8
        for (int kk = 0; kk < 32; kk++) {
            float4 bv = *(const float4*)&Ws[buf][kk * 128 + tx * 4];
            float av[4];
#pragma unroll
            for (int jr = 0; jr < 4; jr++) av[jr] = As[buf][(ty + jr * 8) * 36 + kk];
#pragma unroll
            for (int jr = 0; jr < 4; jr++) {
                acc[jr][0] += av[jr] * bv.x;
                acc[jr][1] += av[jr] * bv.y;
                acc[jr][2] += av[jr] * bv.z;
                acc[jr][3] += av[jr] * bv.w;
            }
        }
        if (kt < 15) {
            int nb = (kt + 1) & 1;
            *(float4*)&As[nb][arow * 36 + ak] = areg;
#pragma unroll
            for (int j = 0; j < 4; j++)
                *(float4*)&Ws[nb][(wrow + j * 8) * 128 + wc] = wreg[j];
        }
    }

    // epilogue: fused LSTM cell. thread owns cols n = n0c + tx*4 .. +3 (one h unit)
    int hh = (n0c >> 2) + tx;
    int n = n0c + tx * 4;
#pragma unroll
    for (int jr = 0; jr < 4; jr++) {
        int row = r0 + ty + jr * 8;
        float4 xr = *(const float4*)(Xp + (long)row * G4 + n);
        float gi = acc[jr][0] + xr.x;
        float gf = acc[jr][1] + xr.y;
        float gg = acc[jr][2] + xr.z;
        float go = acc[jr][3] + xr.w;
        float si = 1.f / (1.f + expf(-gi));
        float sf = 1.f / (1.f + expf(-gf));
        float so = 1.f / (1.f + expf(-go));
        float tg = tanhf(gg);
        float c = sf * cstp[row * Hd + hh] + si * tg;
        float h = so * tanhf(c);
        cstp[row * Hd + hh] = c;
        houtp[row * Hd + hh] = h;
        if (lay == 0) g_hs[d][s][row][hh] = h;
    }
}

// =========================================================================
// layer1 input projections for word w, double-buffered. K=1024.
// grid ((w+1)*5, 16, 2), block 256.
// =========================================================================
__global__ void __launch_bounds__(256)
k_zproj2(int w) {
    __shared__ float As[2][32 * 36];
    __shared__ float Ws[2][32 * 128];
    int bm = blockIdx.x, bn = blockIdx.y, d = blockIdx.z;
    int tid = threadIdx.x;
    int m0 = bm * 32;
    int t = m0 / Rd;
    int r0 = m0 % Rd;
    int tb = w - t;
    int n0c = bn * 128;

    const float* hf = &g_hs[0][t][0][0];
    const float* hb = &g_hs[1][tb][0][0];
    const float* Wp = &g_WihP1[d][0][0];

    int tx = tid & 31, ty = tid >> 5;
    int arow = tid >> 3, ak = (tid & 7) * 4;
    int wrow = tid >> 5, wc = (tid & 31) * 4;

    float acc[4][4];
#pragma unroll
    for (int a = 0; a < 4; a++)
#pragma unroll
        for (int c = 0; c < 4; c++) acc[a][c] = 0.f;

    float4 areg, wreg[4];
    // prologue (kb = 0 < 512 → forward half)
    areg = *(const float4*)&hf[(r0 + arow) * Hd + ak];
#pragma unroll
    for (int j = 0; j < 4; j++)
        wreg[j] = *(const float4*)&Wp[(long)(wrow + j * 8) * G4 + n0c + wc];
    *(float4*)&As[0][arow * 36 + ak] = areg;
#pragma unroll
    for (int j = 0; j < 4; j++)
        *(float4*)&Ws[0][(wrow + j * 8) * 128 + wc] = wreg[j];

    for (int kt = 0; kt < 32; kt++) {
        __syncthreads();
        int buf = kt & 1;
        if (kt < 31) {
            int kb = (kt + 1) * 32;
            const float* src = (kb < Hd) ? (hf + (r0 + arow) * Hd + kb + ak)
                                         : (hb + (r0 + arow) * Hd + (kb - Hd) + ak);
            areg = *(const float4*)src;
#pragma unroll
            for (int j = 0; j < 4; j++)
                wreg[j] = *(const float4*)&Wp[(long)(kb + wrow + j * 8) * G4 + n0c + wc];
        }
#pragma unroll 8
        for (int kk = 0; kk < 32; kk++) {
            float4 bv = *(const float4*)&Ws[buf][kk * 128 + tx * 4];
            float av[4];
#pragma unroll
            for (int jr = 0; jr < 4; jr++) av[jr] = As[buf][(ty + jr * 8) * 36 + kk];
#pragma unroll
            for (int jr = 0; jr < 4; jr++) {
                acc[jr][0] += av[jr] * bv.x;
                acc[jr][1] += av[jr] * bv.y;
                acc[jr][2] += av[jr] * bv.z;
                acc[jr][3] += av[jr] * bv.w;
            }
        }
        if (kt < 31) {
            int nb = (kt + 1) & 1;
            *(float4*)&As[nb][arow * 36 + ak] = areg;
#pragma unroll
            for (int j = 0; j < 4; j++)
                *(float4*)&Ws[nb][(wrow + j * 8) * 128 + wc] = wreg[j];
        }
    }

    int n = n0c + tx * 4;
    const float4 bb = *(const float4*)&g_bP1[d][n];
#pragma unroll
    for (int jr = 0; jr < 4; jr++) {
        int r = r0 + ty + jr * 8;
        float4 o;
        o.x = acc[jr][0] + bb.x;
        o.y = acc[jr][1] + bb.y;
        o.z = acc[jr][2] + bb.z;
        o.w = acc[jr][3] + bb.w;
        *(float4*)&g_Z[d][t][r][n] = o;
    }
}

// ---------------- pack final layer1 states ----------------
__global__ void k_packst(int w, int pb) {
    int i = blockIdx.x * blockDim.x + threadIdx.x;
    if (i >= Rd * 2 * Hd) return;
    int r = i / (2 * Hd), k = i % (2 * Hd);
    int nc = r >> 5, b = r & 31;
    float v = (k < Hd) ? g_hbuf[pb][1][1][r][k]
                       : g_hbuf[pb][1][0][r][k - Hd];
    g_packed[(nc * Td + w) * Bd + b][k] = v;
}

// =========================================================================
// final vocab projection, double-buffered. grid (100, 239), block 256.
// =========================================================================
__global__ void __launch_bounds__(256)
k_final2(const float* __restrict__ Wfc, const float* __restrict__ bfc,
         float* __restrict__ out) {
    __shared__ float As[2][32 * 33];
    __shared__ float Ws[2][128 * 33];
    int bm = blockIdx.x, bn = blockIdx.y;
    int tid = threadIdx.x;
    int m0 = bm * 32, n0 = bn * 128;
    int tx = tid & 31, ty = tid >> 5;
    int lr = tid >> 5, kkA = tid & 31;       // A staging: 4 rows/thread (lr + i*8)
    int nn = tid >> 5, kkW = tid & 31;       // W staging: 16 n-rows/thread (nn + i*8)

    float acc[4][4];
#pragma unroll
    for (int a = 0; a < 4; a++)
#pragma unroll
        for (int c = 0; c < 4; c++) acc[a][c] = 0.f;

    float areg[4], wreg[16];
    // prologue tile 0
#pragma unroll
    for (int i = 0; i < 4; i++)
        areg[i] = g_packed[m0 + lr + i * 8][kkA];
#pragma unroll
    for (int i = 0; i < 16; i++) {
        int n = n0 + nn + i * 8;
        wreg[i] = (n < Vd) ? Wfc[(long)n * (2 * Hd) + kkW] : 0.f;
    }
#pragma unroll
    for (int i = 0; i < 4; i++) As[0][(lr + i * 8) * 33 + kkA] = areg[i];
#pragma unroll
    for (int i = 0; i < 16; i++) Ws[0][(nn + i * 8) * 33 + kkW] = wreg[i];

    for (int kt = 0; kt < 32; kt++) {
        __syncthreads();
        int buf = kt & 1;
        if (kt < 31) {
            int kb = (kt + 1) * 32;
#pragma unroll
            for (int i = 0; i < 4; i++)
                areg[i] = g_packed[m0 + lr + i * 8][kb + kkA];
#pragma unroll
            for (int i = 0; i < 16; i++) {
                int n = n0 + nn + i * 8;
                wreg[i] = (n < Vd) ? Wfc[(long)n * (2 * Hd) + kb + kkW] : 0.f;
            }
        }
#pragma unroll 8
        for (int kk = 0; kk < 32; kk++) {
            float av[4], bv[4];
#pragma unroll
            for (int jr = 0; jr < 4; jr++) av[jr] = As[buf][(ty + jr * 8) * 33 + kk];
#pragma unroll
            for (int jc = 0; jc < 4; jc++) bv[jc] = Ws[buf][(tx + jc * 32) * 33 + kk];
#pragma unroll
            for (int jr = 0; jr < 4; jr++)
#pragma unroll
                for (int jc = 0; jc < 4; jc++) acc[jr][jc] += av[jr] * bv[jc];
        }
        if (kt < 31) {
            int nb = (kt + 1) & 1;
#pragma unroll
            for (int i = 0; i < 4; i++) As[nb][(lr + i * 8) * 33 + kkA] = areg[i];
#pragma unroll
            for (int i = 0; i < 16; i++) Ws[nb][(nn + i * 8) * 33 + kkW] = wreg[i];
        }
    }

#pragma unroll
    for (int jr = 0; jr < 4; jr++) {
        int m = m0 + ty + jr * 8;
#pragma unroll
        for (int jc = 0; jc < 4; jc++) {
            int n = n0 + tx + jc * 32;
            if (n < Vd) out[(long)m * Vd + n] = acc[jr][jc] + bfc[n];
        }
    }
}

// ---------------- host orchestration ----------------
extern "C" void kernel_launch(void* const* d_in, const int* in_sizes, int n_in,
                              void* d_out, int out_size) {
    const float* img  = (const float*)d_in[0];
    const int*   cap  = (const int*)d_in[1];
    const float* emb  = (const float*)d_in[2];
    const float* Wh   = (const float*)d_in[3];
    const float* bh   = (const float*)d_in[4];
    const float* Wc   = (const float*)d_in[5];
    const float* bc   = (const float*)d_in[6];
    const float* Wih0 = (const float*)d_in[7];
    const float* Whh0 = (const float*)d_in[8];
    const float* bih0 = (const float*)d_in[9];
    const float* bhh0 = (const float*)d_in[10];
    const float* Wih1 = (const float*)d_in[11];
    const float* Whh1 = (const float*)d_in[12];
    const float* bih1 = (const float*)d_in[13];
    const float* bhh1 = (const float*)d_in[14];
    const float* Wfc  = (const float*)d_in[15];
    const float* bfc  = (const float*)d_in[16];
    float* out = (float*)d_out;

    k_pack<<<dim3(16384, 6), 256>>>(Wih0, Whh0, bih0, bhh0, Wih1, Whh1, bih1, bhh1);
    k_init<<<(2 * Bd * Hd + 255) / 256, 256>>>(img, Wh, bh, Wc, bc);
    k_xproj<<<dim3(100, 16, 2), 256>>>(emb, cap);

    int p0 = 0, p1 = 0;
    // prelude: layer0 of word 0 (single step)
    k_step2<<<dim3(5, 16, 4), 256>>>(p0, 0, 0, 1, p1, 0, 0, 0);
    p0 ^= 1;
    k_zproj2<<<dim3(5, 16, 2), 256>>>(0);

    for (int w = 0; w < Td; w++) {
        int s0max = (w + 1 < Td) ? (w + 1) : -1;  // layer0 word w+1 steps
        int s1max = w;                             // layer1 word w steps
        int smax = s0max > s1max ? s0max : s1max;
        for (int s = 0; s <= smax; s++) {
            int a0 = (s <= s0max) ? 1 : 0;
            int a1 = (s <= s1max) ? 1 : 0;
            k_step2<<<dim3(5, 16, 4), 256>>>(p0, s, w + 1, a0, p1, s, w, a1);
            if (a0) p0 ^= 1;
            if (a1) p1 ^= 1;
        }
        k_packst<<<(Rd * 2 * Hd + 255) / 256, 256>>>(w, p1);
        if (w + 1 < Td)
            k_zproj2<<<dim3((w + 2) * 5, 16, 2), 256>>>(w + 1);
    }
    k_final2<<<dim3(100, 239), 256>>>(Wfc, bfc, out);
}

// round 5
// speedup vs baseline: 2.8748x; 1.3747x over previous
#include <cuda_runtime.h>
#include <cuda_bf16.h>
#include <math.h>
#include <stdint.h>

// Problem constants
#define Hd   512
#define G4   2048      // 4*H
#define Ed   250
#define Bd   32
#define NCd  5
#define Td   20
#define Rd   160       // NC*B
#define Vd   30522
#define CNNd 2048
#define Md   3200      // NC*T*B
#define Kfc  1024      // 2*H
#define PITCH 40       // smem row pitch in bf16 elems (80B, bank-conflict-free)

// ---------------- device scratch (no allocations allowed) ----------------
__device__ float g_WihP0[2][Ed][G4];
__device__ float g_WhhP0[2][Hd][G4];
__device__ float g_WhhP1[2][Hd][G4];
__device__ float g_bP0[2][G4];
__device__ float g_bP1[2][G4];
__device__ float g_X0[2][Td][Rd][G4];        // layer0 input projections (+bias)
__device__ float g_Z[2][Td][Rd][G4];         // layer1 input projections (+bias)
__device__ float g_hbuf[2][2][2][Rd][Hd];    // [parity][layer][dir][row][h]
__device__ float g_cS[2][2][Rd][Hd];         // [layer][dir][row][h]
// bf16 hi/lo split activations (A operands for mma GEMMs)
__device__ __nv_bfloat16 g_hsH[2][Td][Rd][Hd];
__device__ __nv_bfloat16 g_hsL[2][Td][Rd][Hd];
__device__ __nv_bfloat16 g_packedH[Md][Kfc];
__device__ __nv_bfloat16 g_packedL[Md][Kfc];
// bf16 hi/lo split weights (B operands, K-major rows)
__device__ __nv_bfloat16 g_WfcH[(long)Vd * Kfc];
__device__ __nv_bfloat16 g_WfcL[(long)Vd * Kfc];
__device__ __nv_bfloat16 g_W1H[2L * G4 * Kfc];   // gate-interleaved [d][n][k]
__device__ __nv_bfloat16 g_W1L[2L * G4 * Kfc];

__device__ __forceinline__ uint32_t smem_u32(const void* p) {
    uint32_t a;
    asm("{ .reg .u64 t; cvta.to.shared.u64 t, %1; cvt.u32.u64 %0, t; }"
        : "=r"(a) : "l"(p));
    return a;
}
#define LDSM4(r, addr) \
    asm volatile("ldmatrix.sync.aligned.m8n8.x4.shared.b16 {%0,%1,%2,%3}, [%4];" \
        : "=r"((r)[0]), "=r"((r)[1]), "=r"((r)[2]), "=r"((r)[3]) : "r"(addr))
#define MMA16816(c, a, b) \
    asm volatile("mma.sync.aligned.m16n8k16.row.col.f32.bf16.bf16.f32 " \
        "{%0,%1,%2,%3}, {%4,%5,%6,%7}, {%8,%9}, {%0,%1,%2,%3};" \
        : "+f"((c)[0]), "+f"((c)[1]), "+f"((c)[2]), "+f"((c)[3]) \
        : "r"((a)[0]), "r"((a)[1]), "r"((a)[2]), "r"((a)[3]), "r"((b)[0]), "r"((b)[1]))

// ---------------- weight packing (fp32, gate-interleaved) ----------------
__global__ void k_pack(const float* __restrict__ Wih0, const float* __restrict__ Whh0,
                       const float* __restrict__ bih0, const float* __restrict__ bhh0,
                       const float* __restrict__ Whh1,
                       const float* __restrict__ bih1, const float* __restrict__ bhh1) {
    int region = blockIdx.y;
    long i = (long)blockIdx.x * blockDim.x + threadIdx.x;
    if (region == 0) {
        if (i >= 2L * Ed * G4) return;
        int d = (int)(i / (Ed * G4)); int rem = (int)(i % (Ed * G4));
        int k = rem / G4, n = rem % G4;
        int h = n >> 2, g = n & 3;
        g_WihP0[d][k][n] = Wih0[((long)d * G4 + g * Hd + h) * Ed + k];
    } else if (region == 1) {
        if (i >= 2L * Hd * G4) return;
        int d = (int)(i / (Hd * G4)); int rem = (int)(i % (Hd * G4));
        int k = rem / G4, n = rem % G4;
        int h = n >> 2, g = n & 3;
        g_WhhP0[d][k][n] = Whh0[((long)d * G4 + g * Hd + h) * Hd + k];
    } else if (region == 2) {
        if (i >= 2L * Hd * G4) return;
        int d = (int)(i / (Hd * G4)); int rem = (int)(i % (Hd * G4));
        int k = rem / G4, n = rem % G4;
        int h = n >> 2, g = n & 3;
        g_WhhP1[d][k][n] = Whh1[((long)d * G4 + g * Hd + h) * Hd + k];
    } else if (region == 3) {
        if (i >= 2L * G4) return;
        int d = (int)(i / G4); int n = (int)(i % G4);
        int h = n >> 2, g = n & 3;
        long j = (long)d * G4 + g * Hd + h;
        g_bP0[d][n] = bih0[j] + bhh0[j];
    } else {
        if (i >= 2L * G4) return;
        int d = (int)(i / G4); int n = (int)(i % G4);
        int h = n >> 2, g = n & 3;
        long j = (long)d * G4 + g * Hd + h;
        g_bP1[d][n] = bih1[j] + bhh1[j];
    }
}

// ---------------- bf16 hi/lo split packing for tensor-core GEMMs ----------------
__global__ void k_packbf(const float* __restrict__ Wfc, const float* __restrict__ Wih1) {
    long i = (long)blockIdx.x * blockDim.x + threadIdx.x;
    if (blockIdx.y == 0) {
        if (i >= (long)Vd * Kfc) return;
        float x = Wfc[i];
        __nv_bfloat16 h = __float2bfloat16(x);
        g_WfcH[i] = h;
        g_WfcL[i] = __float2bfloat16(x - __bfloat162float(h));
    } else {
        if (i >= 2L * G4 * Kfc) return;
        int d = (int)(i / (G4 * Kfc)); long rem = i % ((long)G4 * Kfc);
        int n = (int)(rem / Kfc), k = (int)(rem % Kfc);
        int h = n >> 2, g = n & 3;
        float x = Wih1[((long)d * G4 + g * Hd + h) * Kfc + k];
        __nv_bfloat16 hb = __float2bfloat16(x);
        g_W1H[i] = hb;
        g_W1L[i] = __float2bfloat16(x - __bfloat162float(hb));
    }
}

// ---------------- initial states ----------------
__global__ void k_init(const float* __restrict__ img, const float* __restrict__ Wh,
                       const float* __restrict__ bh, const float* __restrict__ Wc,
                       const float* __restrict__ bc) {
    int i = blockIdx.x * blockDim.x + threadIdx.x;
    if (i >= 2 * Bd * Hd) return;
    int which = i / (Bd * Hd);
    int rem = i % (Bd * Hd);
    int b = rem / Hd, j = rem % Hd;
    const float* W = which ? Wc : Wh;
    const float* bias = which ? bc : bh;
    const float4* a4 = (const float4*)(img + (long)b * CNNd);
    const float4* w4 = (const float4*)(W + (long)j * CNNd);
    float acc = 0.f;
#pragma unroll 4
    for (int k = 0; k < CNNd / 4; k++) {
        float4 a = a4[k], w = w4[k];
        acc += a.x * w.x + a.y * w.y + a.z * w.z + a.w * w.w;
    }
    float v = fmaxf(acc + bias[j], 0.f);
    for (int nc = 0; nc < NCd; nc++) {
        int row = nc * Bd + b;
        for (int l = 0; l < 2; l++)
            for (int d = 0; d < 2; d++) {
                if (which == 0) g_hbuf[0][l][d][row][j] = v;
                else            g_cS[l][d][row][j] = v;
            }
    }
}

// ---------------- layer0 input projections for all t ----------------
__global__ void k_xproj(const float* __restrict__ emb, const int* __restrict__ cap) {
    __shared__ float xs[32 * Ed];
    __shared__ int toks[32];
    int bm = blockIdx.x, bn = blockIdx.y, d = blockIdx.z;
    int tid = threadIdx.x;
    if (tid < 32) {
        int m = bm * 32 + tid;
        int t = m / Rd, r = m % Rd;
        int nc = r >> 5, b = r & 31;
        toks[tid] = cap[b * (NCd * Td) + nc * Td + t];
    }
    __syncthreads();
    for (int e = tid; e < 32 * Ed; e += 256) {
        int lr = e / Ed, k = e % Ed;
        xs[e] = emb[(long)toks[lr] * Ed + k];
    }
    __syncthreads();
    int tx = tid & 31, ty = tid >> 5;
    float acc[4][4];
#pragma unroll
    for (int a = 0; a < 4; a++)
#pragma unroll
        for (int c = 0; c < 4; c++) acc[a][c] = 0.f;
    int n0 = bn * 128;
    const float* Bp = &g_WihP0[d][0][0];
#pragma unroll 5
    for (int k = 0; k < Ed; k++) {
        float av[4], bv[4];
#pragma unroll
        for (int jr = 0; jr < 4; jr++) av[jr] = xs[(ty + jr * 8) * Ed + k];
#pragma unroll
        for (int jc = 0; jc < 4; jc++) bv[jc] = Bp[(long)k * G4 + n0 + tx + jc * 32];
#pragma unroll
        for (int jr = 0; jr < 4; jr++)
#pragma unroll
            for (int jc = 0; jc < 4; jc++) acc[jr][jc] += av[jr] * bv[jc];
    }
    int m0 = bm * 32;
#pragma unroll
    for (int jr = 0; jr < 4; jr++) {
        int m = m0 + ty + jr * 8;
        int t = m / Rd, r = m % Rd;
#pragma unroll
        for (int jc = 0; jc < 4; jc++) {
            int n = n0 + tx + jc * 32;
            g_X0[d][t][r][n] = acc[jr][jc] + g_bP0[d][n];
        }
    }
}

// =========================================================================
// bf16-split mma.sync GEMM (HMMA path, compiles for sm_103).
// mode 0: out[M=3200][Vd] = packed @ Wfc^T + bfc   grid (25, 239, 1)
// mode 1: Z[d][t][r][:] = Y @ W1^T + bP1           grid (Mtiles, 16, 2)
// Block tile 128x128, K-chunk 32, K=1024 (32 chunks), double-buffered smem.
// C = Ah*Bh + Ah*Bl + Al*Bh  (3-term split, err ~1e-5)
// =========================================================================
__global__ void __launch_bounds__(256, 1)
k_mma(int mode, int w, const float* __restrict__ bfc, float* __restrict__ out) {
    extern __shared__ __align__(16) char dsm[];
    __nv_bfloat16* sA_h = (__nv_bfloat16*)dsm;       // [2][128*PITCH]
    __nv_bfloat16* sA_l = sA_h + 2 * 128 * PITCH;
    __nv_bfloat16* sB_h = sA_l + 2 * 128 * PITCH;
    __nv_bfloat16* sB_l = sB_h + 2 * 128 * PITCH;
    uint32_t uAh = smem_u32(sA_h), uAl = smem_u32(sA_l);
    uint32_t uBh = smem_u32(sB_h), uBl = smem_u32(sB_l);

    int tid = threadIdx.x;
    int lane = tid & 31, wid = tid >> 5;
    int wm = wid >> 1, wn = wid & 1;                 // warp grid 4(m) x 2(n)
    int m0 = blockIdx.x * 128, n0 = blockIdx.y * 128, dz = blockIdx.z;
    int Mtot = mode ? (w + 1) * Rd : Md;

    // staging coords: thread covers row sr, k-half kh (16 elems)
    int sr = tid & 127, kh = tid >> 7;
    int k0 = kh * 16;

    // A source row
    int am = m0 + sr; if (am >= Mtot) am = Mtot - 1;
    int att = 0, arr = 0;
    const __nv_bfloat16 *aH0 = nullptr, *aL0 = nullptr;
    if (mode == 0) { aH0 = &g_packedH[am][0]; aL0 = &g_packedL[am][0]; }
    else { att = am / Rd; arr = am - att * Rd; }

    // B source row
    int bnr = n0 + sr;
    bool bvalid = mode ? true : (bnr < Vd);
    const __nv_bfloat16* BH = mode ? g_W1H : g_WfcH;
    const __nv_bfloat16* BL = mode ? g_W1L : g_WfcL;
    long boff = mode ? ((long)dz * G4 + bnr) * Kfc : (long)bnr * Kfc;

    float c[2][8][4];
#pragma unroll
    for (int mt = 0; mt < 2; mt++)
#pragma unroll
        for (int nt = 0; nt < 8; nt++)
#pragma unroll
            for (int q = 0; q < 4; q++) c[mt][nt][q] = 0.f;

    uint4 vA[4], vB[4];

    auto LOAD = [&](int kc) {
        int kb = kc * 32 + k0;
        if (mode == 0) {
            vA[0] = *(const uint4*)(aH0 + kb);
            vA[1] = *(const uint4*)(aH0 + kb + 8);
            vA[2] = *(const uint4*)(aL0 + kb);
            vA[3] = *(const uint4*)(aL0 + kb + 8);
        } else {
#pragma unroll
            for (int q = 0; q < 2; q++) {
                int kg = kb + q * 8;
                const __nv_bfloat16* pH = (kg < Hd) ? &g_hsH[0][att][arr][kg]
                                                    : &g_hsH[1][w - att][arr][kg - Hd];
                const __nv_bfloat16* pL = (kg < Hd) ? &g_hsL[0][att][arr][kg]
                                                    : &g_hsL[1][w - att][arr][kg - Hd];
                vA[q] = *(const uint4*)pH;
                vA[2 + q] = *(const uint4*)pL;
            }
        }
        if (bvalid) {
            vB[0] = *(const uint4*)(BH + boff + kb);
            vB[1] = *(const uint4*)(BH + boff + kb + 8);
            vB[2] = *(const uint4*)(BL + boff + kb);
            vB[3] = *(const uint4*)(BL + boff + kb + 8);
        } else {
            uint4 z = make_uint4(0, 0, 0, 0);
            vB[0] = z; vB[1] = z; vB[2] = z; vB[3] = z;
        }
    };
    auto STORE = [&](int buf) {
        int base = buf * 128 * PITCH + sr * PITCH + k0;
        *(uint4*)&sA_h[base] = vA[0]; *(uint4*)&sA_h[base + 8] = vA[1];
        *(uint4*)&sA_l[base] = vA[2]; *(uint4*)&sA_l[base + 8] = vA[3];
        *(uint4*)&sB_h[base] = vB[0]; *(uint4*)&sB_h[base + 8] = vB[1];
        *(uint4*)&sB_l[base] = vB[2]; *(uint4*)&sB_l[base + 8] = vB[3];
    };
    auto COMPUTE = [&](int buf) {
        uint32_t bo = (uint32_t)buf * 128 * PITCH * 2;   // byte offset
#pragma unroll
        for (int k16 = 0; k16 < 2; k16++) {
            int ar = lane & 15;
            int acs = k16 * 16 + ((lane >> 4) << 3);
            uint32_t ah[2][4], al[2][4];
#pragma unroll
            for (int mt = 0; mt < 2; mt++) {
                uint32_t off = bo + (uint32_t)((wm * 32 + mt * 16 + ar) * PITCH + acs) * 2;
                LDSM4(ah[mt], uAh + off);
                LDSM4(al[mt], uAl + off);
            }
            int br = (lane & 7) + ((lane >> 4) << 3);
            int bcs = k16 * 16 + (((lane >> 3) & 1) << 3);
            uint32_t bh[8][2], bl[8][2];
#pragma unroll
            for (int ntp = 0; ntp < 4; ntp++) {
                uint32_t off = bo + (uint32_t)((wn * 64 + ntp * 16 + br) * PITCH + bcs) * 2;
                uint32_t r4[4];
                LDSM4(r4, uBh + off);
                bh[ntp * 2][0] = r4[0]; bh[ntp * 2][1] = r4[1];
                bh[ntp * 2 + 1][0] = r4[2]; bh[ntp * 2 + 1][1] = r4[3];
                LDSM4(r4, uBl + off);
                bl[ntp * 2][0] = r4[0]; bl[ntp * 2][1] = r4[1];
                bl[ntp * 2 + 1][0] = r4[2]; bl[ntp * 2 + 1][1] = r4[3];
            }
#pragma unroll
            for (int mt = 0; mt < 2; mt++)
#pragma unroll
                for (int nt = 0; nt < 8; nt++) {
                    MMA16816(c[mt][nt], ah[mt], bh[nt]);
                    MMA16816(c[mt][nt], ah[mt], bl[nt]);
                    MMA16816(c[mt][nt], al[mt], bh[nt]);
                }
        }
    };

    LOAD(0); STORE(0);
    __syncthreads();
    for (int kc = 0; kc < 32; kc++) {
        int buf = kc & 1;
        if (kc < 31) LOAD(kc + 1);
        COMPUTE(buf);
        if (kc < 31) STORE(buf ^ 1);
        __syncthreads();
    }

    // epilogue: fragment layout stores (lane l: row +l/4, col +2*(l%4))
    int qrow = lane >> 2, qcol = (lane & 3) * 2;
#pragma unroll
    for (int mt = 0; mt < 2; mt++) {
#pragma unroll
        for (int nt = 0; nt < 8; nt++) {
            int n = n0 + wn * 64 + nt * 8 + qcol;
            int mA = m0 + wm * 32 + mt * 16 + qrow;
            if (mode == 0) {
                if (n < Vd) {
                    float2 bb = *(const float2*)&bfc[n];
                    float2 o0 = make_float2(c[mt][nt][0] + bb.x, c[mt][nt][1] + bb.y);
                    float2 o1 = make_float2(c[mt][nt][2] + bb.x, c[mt][nt][3] + bb.y);
                    *(float2*)&out[(long)mA * Vd + n] = o0;
                    *(float2*)&out[(long)(mA + 8) * Vd + n] = o1;
                }
            } else {
                float2 bb = *(const float2*)&g_bP1[dz][n];
                if (mA < Mtot) {
                    int t = mA / Rd, rr = mA - t * Rd;
                    *(float2*)&g_Z[dz][t][rr][n] =
                        make_float2(c[mt][nt][0] + bb.x, c[mt][nt][1] + bb.y);
                }
                if (mA + 8 < Mtot) {
                    int t = (mA + 8) / Rd, rr = (mA + 8) - t * Rd;
                    *(float2*)&g_Z[dz][t][rr][n] =
                        make_float2(c[mt][nt][2] + bb.x, c[mt][nt][3] + bb.y);
                }
            }
        }
    }
}

// =========================================================================
// Combined pipelined LSTM step (FFMA). layer0 epilogue now emits bf16 hi/lo.
// =========================================================================
__global__ void __launch_bounds__(256)
k_step2(int p0, int s0, int w0, int act0, int p1, int s1, int w1, int act1) {
    __shared__ float As[2][32 * 36];
    __shared__ float Ws[2][32 * 128];

    int z = blockIdx.z;
    int lay = z >> 1, d = z & 1;
    int act = lay ? act1 : act0;
    if (!act) return;
    int p = lay ? p1 : p0;
    int s = lay ? s1 : s0;
    int w = lay ? w1 : w0;

    int bm = blockIdx.x, bn = blockIdx.y;
    int tid = threadIdx.x;
    int r0 = bm * 32;
    int n0c = bn * 128;

    const float* hinp = &g_hbuf[p][lay][d][0][0];
    float* houtp = &g_hbuf[p ^ 1][lay][d][0][0];
    float* cstp = &g_cS[lay][d][0][0];
    const float* Wp = lay ? &g_WhhP1[d][0][0] : &g_WhhP0[d][0][0];
    int xidx = d ? (w - s) : s;
    const float* Xp = lay ? &g_Z[d][xidx][0][0] : &g_X0[d][xidx][0][0];

    int tx = tid & 31, ty = tid >> 5;
    int arow = tid >> 3, ak = (tid & 7) * 4;
    int wrow = tid >> 5, wc = (tid & 31) * 4;

    float acc[4][4];
#pragma unroll
    for (int a = 0; a < 4; a++)
#pragma unroll
        for (int c = 0; c < 4; c++) acc[a][c] = 0.f;

    float4 areg, wreg[4];
    areg = *(const float4*)&hinp[(r0 + arow) * Hd + ak];
#pragma unroll
    for (int j = 0; j < 4; j++)
        wreg[j] = *(const float4*)&Wp[(long)(wrow + j * 8) * G4 + n0c + wc];
    *(float4*)&As[0][arow * 36 + ak] = areg;
#pragma unroll
    for (int j = 0; j < 4; j++)
        *(float4*)&Ws[0][(wrow + j * 8) * 128 + wc] = wreg[j];

    for (int kt = 0; kt < 16; kt++) {
        __syncthreads();
        int buf = kt & 1;
        if (kt < 15) {
            int kb = (kt + 1) * 32;
            areg = *(const float4*)&hinp[(r0 + arow) * Hd + kb + ak];
#pragma unroll
            for (int j = 0; j < 4; j++)
                wreg[j] = *(const float4*)&Wp[(long)(kb + wrow + j * 8) * G4 + n0c + wc];
        }
#pragma unroll 8
        for (int kk = 0; kk < 32; kk++) {
            float4 bv = *(const float4*)&Ws[buf][kk * 128 + tx * 4];
            float av[4];
#pragma unroll
            for (int jr = 0; jr < 4; jr++) av[jr] = As[buf][(ty + jr * 8) * 36 + kk];
#pragma unroll
            for (int jr = 0; jr < 4; jr++) {
                acc[jr][0] += av[jr] * bv.x;
                acc[jr][1] += av[jr] * bv.y;
                acc[jr][2] += av[jr] * bv.z;
                acc[jr][3] += av[jr] * bv.w;
            }
        }
        if (kt < 15) {
            int nb = (kt + 1) & 1;
            *(float4*)&As[nb][arow * 36 + ak] = areg;
#pragma unroll
            for (int j = 0; j < 4; j++)
                *(float4*)&Ws[nb][(wrow + j * 8) * 128 + wc] = wreg[j];
        }
    }

    int hh = (n0c >> 2) + tx;
    int n = n0c + tx * 4;
#pragma unroll
    for (int jr = 0; jr < 4; jr++) {
        int row = r0 + ty + jr * 8;
        float4 xr = *(const float4*)(Xp + (long)row * G4 + n);
        float gi = acc[jr][0] + xr.x;
        float gf = acc[jr][1] + xr.y;
        float gg = acc[jr][2] + xr.z;
        float go = acc[jr][3] + xr.w;
        float si = 1.f / (1.f + expf(-gi));
        float sf = 1.f / (1.f + expf(-gf));
        float so = 1.f / (1.f + expf(-go));
        float tg = tanhf(gg);
        float cc = sf * cstp[row * Hd + hh] + si * tg;
        float h = so * tanhf(cc);
        cstp[row * Hd + hh] = cc;
        houtp[row * Hd + hh] = h;
        if (lay == 0) {
            __nv_bfloat16 hb = __float2bfloat16(h);
            g_hsH[d][s][row][hh] = hb;
            g_hsL[d][s][row][hh] = __float2bfloat16(h - __bfloat162float(hb));
        }
    }
}

// ---------------- pack final layer1 states (bf16 hi/lo) ----------------
__global__ void k_packst(int w, int pb) {
    int i = blockIdx.x * blockDim.x + threadIdx.x;
    if (i >= Rd * 2 * Hd) return;
    int r = i / (2 * Hd), k = i % (2 * Hd);
    int nc = r >> 5, b = r & 31;
    float v = (k < Hd) ? g_hbuf[pb][1][1][r][k]
                       : g_hbuf[pb][1][0][r][k - Hd];
    int m = (nc * Td + w) * Bd + b;
    __nv_bfloat16 hv = __float2bfloat16(v);
    g_packedH[m][k] = hv;
    g_packedL[m][k] = __float2bfloat16(v - __bfloat162float(hv));
}

// ---------------- host orchestration ----------------
#define MMA_SMEM (8 * 128 * PITCH * 2)   // 81920 bytes

extern "C" void kernel_launch(void* const* d_in, const int* in_sizes, int n_in,
                              void* d_out, int out_size) {
    const float* img  = (const float*)d_in[0];
    const int*   cap  = (const int*)d_in[1];
    const float* emb  = (const float*)d_in[2];
    const float* Wh   = (const float*)d_in[3];
    const float* bh   = (const float*)d_in[4];
    const float* Wc   = (const float*)d_in[5];
    const float* bc   = (const float*)d_in[6];
    const float* Wih0 = (const float*)d_in[7];
    const float* Whh0 = (const float*)d_in[8];
    const float* bih0 = (const float*)d_in[9];
    const float* bhh0 = (const float*)d_in[10];
    const float* Wih1 = (const float*)d_in[11];
    const float* Whh1 = (const float*)d_in[12];
    const float* bih1 = (const float*)d_in[13];
    const float* bhh1 = (const float*)d_in[14];
    const float* Wfc  = (const float*)d_in[15];
    const float* bfc  = (const float*)d_in[16];
    float* out = (float*)d_out;

    cudaFuncSetAttribute(k_mma, cudaFuncAttributeMaxDynamicSharedMemorySize, MMA_SMEM);

    k_pack<<<dim3(8192, 5), 256>>>(Wih0, Whh0, bih0, bhh0, Whh1, bih1, bhh1);
    k_packbf<<<dim3(122088, 2), 256>>>(Wfc, Wih1);
    k_init<<<(2 * Bd * Hd + 255) / 256, 256>>>(img, Wh, bh, Wc, bc);
    k_xproj<<<dim3(100, 16, 2), 256>>>(emb, cap);

    int p0 = 0, p1 = 0;
    // prelude: layer0 of word 0 (single step), then Z(0)
    k_step2<<<dim3(5, 16, 4), 256>>>(p0, 0, 0, 1, p1, 0, 0, 0);
    p0 ^= 1;
    k_mma<<<dim3(2, 16, 2), 256, MMA_SMEM>>>(1, 0, nullptr, nullptr);

    for (int w = 0; w < Td; w++) {
        int s0max = (w + 1 < Td) ? (w + 1) : -1;   // layer0 word w+1 steps
        int s1max = w;                              // layer1 word w steps
        int smax = s0max > s1max ? s0max : s1max;
        for (int s = 0; s <= smax; s++) {
            int a0 = (s <= s0max) ? 1 : 0;
            int a1 = (s <= s1max) ? 1 : 0;
            k_step2<<<dim3(5, 16, 4), 256>>>(p0, s, w + 1, a0, p1, s, w, a1);
            if (a0) p0 ^= 1;
            if (a1) p1 ^= 1;
        }
        k_packst<<<(Rd * 2 * Hd + 255) / 256, 256>>>(w, p1);
        if (w + 1 < Td) {
            int Mt = ((w + 2) * Rd + 127) / 128;
            k_mma<<<dim3(Mt, 16, 2), 256, MMA_SMEM>>>(1, w + 1, nullptr, nullptr);
        }
    }
    k_mma<<<dim3(25, 239, 1), 256, MMA_SMEM>>>(0, 0, bfc, out);
}

// round 6
// speedup vs baseline: 3.3244x; 1.1564x over previous
#include <cuda_runtime.h>
#include <cuda_bf16.h>
#include <math.h>
#include <stdint.h>

// Problem constants
#define Hd   512
#define G4   2048      // 4*H
#define Ed   250
#define Bd   32
#define NCd  5
#define Td   20
#define Rd   160       // NC*B
#define Vd   30522
#define CNNd 2048
#define Md   3200      // NC*T*B
#define Kfc  1024      // 2*H
#define PITCH 40       // smem row pitch in bf16 elems (80B, bank-conflict-free)

// ---------------- device scratch (no allocations allowed) ----------------
__device__ float g_WihP0[2][Ed][G4];
__device__ float g_bP0[2][G4];
__device__ float g_bP1[2][G4];
__device__ float g_X0[2][Td][Rd][G4];        // layer0 input projections (+bias)
__device__ float g_Z[2][Td][Rd][G4];         // layer1 input projections (+bias)
__device__ float g_cS[2][2][Rd][Hd];         // [layer][dir][row][h]  fp32 cell state
// LSTM h state as bf16 hi/lo, double buffered: [parity][layer][dir][row][h]
__device__ __nv_bfloat16 g_hbH[2][2][2][Rd][Hd];
__device__ __nv_bfloat16 g_hbL[2][2][2][Rd][Hd];
// bf16 hi/lo split activations (A operands for mma GEMMs)
__device__ __nv_bfloat16 g_hsH[2][Td][Rd][Hd];
__device__ __nv_bfloat16 g_hsL[2][Td][Rd][Hd];
__device__ __nv_bfloat16 g_packedH[Md][Kfc];
__device__ __nv_bfloat16 g_packedL[Md][Kfc];
// bf16 hi/lo split weights (B operands, K-major rows)
__device__ __nv_bfloat16 g_WfcH[(long)Vd * Kfc];
__device__ __nv_bfloat16 g_WfcL[(long)Vd * Kfc];
__device__ __nv_bfloat16 g_W1H[2L * G4 * Kfc];   // gate-interleaved [d][n][k]
__device__ __nv_bfloat16 g_W1L[2L * G4 * Kfc];
__device__ __nv_bfloat16 g_WsH[2][2][G4][Hd];    // recurrent weights [lay][d][n][k]
__device__ __nv_bfloat16 g_WsL[2][2][G4][Hd];

__device__ __forceinline__ uint32_t smem_u32(const void* p) {
    uint32_t a;
    asm("{ .reg .u64 t; cvta.to.shared.u64 t, %1; cvt.u32.u64 %0, t; }"
        : "=r"(a) : "l"(p));
    return a;
}
#define LDSM4(r, addr) \
    asm volatile("ldmatrix.sync.aligned.m8n8.x4.shared.b16 {%0,%1,%2,%3}, [%4];" \
        : "=r"((r)[0]), "=r"((r)[1]), "=r"((r)[2]), "=r"((r)[3]) : "r"(addr))
#define MMA16816(c, a, b) \
    asm volatile("mma.sync.aligned.m16n8k16.row.col.f32.bf16.bf16.f32 " \
        "{%0,%1,%2,%3}, {%4,%5,%6,%7}, {%8,%9}, {%0,%1,%2,%3};" \
        : "+f"((c)[0]), "+f"((c)[1]), "+f"((c)[2]), "+f"((c)[3]) \
        : "r"((a)[0]), "r"((a)[1]), "r"((a)[2]), "r"((a)[3]), "r"((b)[0]), "r"((b)[1]))

// ---------------- weight packing (fp32 for xproj, biases) ----------------
__global__ void k_pack(const float* __restrict__ Wih0,
                       const float* __restrict__ bih0, const float* __restrict__ bhh0,
                       const float* __restrict__ bih1, const float* __restrict__ bhh1) {
    int region = blockIdx.y;
    long i = (long)blockIdx.x * blockDim.x + threadIdx.x;
    if (region == 0) {
        if (i >= 2L * Ed * G4) return;
        int d = (int)(i / (Ed * G4)); int rem = (int)(i % (Ed * G4));
        int k = rem / G4, n = rem % G4;
        int h = n >> 2, g = n & 3;
        g_WihP0[d][k][n] = Wih0[((long)d * G4 + g * Hd + h) * Ed + k];
    } else if (region == 1) {
        if (i >= 2L * G4) return;
        int d = (int)(i / G4); int n = (int)(i % G4);
        int h = n >> 2, g = n & 3;
        long j = (long)d * G4 + g * Hd + h;
        g_bP0[d][n] = bih0[j] + bhh0[j];
    } else {
        if (i >= 2L * G4) return;
        int d = (int)(i / G4); int n = (int)(i % G4);
        int h = n >> 2, g = n & 3;
        long j = (long)d * G4 + g * Hd + h;
        g_bP1[d][n] = bih1[j] + bhh1[j];
    }
}

// ---------------- bf16 hi/lo split packing for tensor-core GEMMs ----------------
__global__ void k_packbf(const float* __restrict__ Wfc, const float* __restrict__ Wih1,
                         const float* __restrict__ Whh0, const float* __restrict__ Whh1) {
    long i = (long)blockIdx.x * blockDim.x + threadIdx.x;
    if (blockIdx.y == 0) {
        if (i >= (long)Vd * Kfc) return;
        float x = Wfc[i];
        __nv_bfloat16 h = __float2bfloat16(x);
        g_WfcH[i] = h;
        g_WfcL[i] = __float2bfloat16(x - __bfloat162float(h));
    } else if (blockIdx.y == 1) {
        if (i >= 2L * G4 * Kfc) return;
        int d = (int)(i / (G4 * Kfc)); long rem = i % ((long)G4 * Kfc);
        int n = (int)(rem / Kfc), k = (int)(rem % Kfc);
        int h = n >> 2, g = n & 3;
        float x = Wih1[((long)d * G4 + g * Hd + h) * Kfc + k];
        __nv_bfloat16 hb = __float2bfloat16(x);
        g_W1H[i] = hb;
        g_W1L[i] = __float2bfloat16(x - __bfloat162float(hb));
    } else {
        if (i >= 2L * 2 * G4 * Hd) return;
        int lay = (int)(i / (2L * G4 * Hd));
        long rem = i % (2L * G4 * Hd);
        int d = (int)(rem / ((long)G4 * Hd));
        long r2 = rem % ((long)G4 * Hd);
        int n = (int)(r2 / Hd), k = (int)(r2 % Hd);
        int h = n >> 2, g = n & 3;
        const float* W = lay ? Whh1 : Whh0;
        float x = W[((long)d * G4 + g * Hd + h) * Hd + k];
        __nv_bfloat16 hb = __float2bfloat16(x);
        g_WsH[lay][d][n][k] = hb;
        g_WsL[lay][d][n][k] = __float2bfloat16(x - __bfloat162float(hb));
    }
}

// ---------------- initial states: bf16 hi/lo h0, fp32 c0 ----------------
__global__ void k_init(const float* __restrict__ img, const float* __restrict__ Wh,
                       const float* __restrict__ bh, const float* __restrict__ Wc,
                       const float* __restrict__ bc) {
    int i = blockIdx.x * blockDim.x + threadIdx.x;
    if (i >= 2 * Bd * Hd) return;
    int which = i / (Bd * Hd);
    int rem = i % (Bd * Hd);
    int b = rem / Hd, j = rem % Hd;
    const float* W = which ? Wc : Wh;
    const float* bias = which ? bc : bh;
    const float4* a4 = (const float4*)(img + (long)b * CNNd);
    const float4* w4 = (const float4*)(W + (long)j * CNNd);
    float acc = 0.f;
#pragma unroll 4
    for (int k = 0; k < CNNd / 4; k++) {
        float4 a = a4[k], w = w4[k];
        acc += a.x * w.x + a.y * w.y + a.z * w.z + a.w * w.w;
    }
    float v = fmaxf(acc + bias[j], 0.f);
    __nv_bfloat16 hv = __float2bfloat16(v);
    __nv_bfloat16 lv = __float2bfloat16(v - __bfloat162float(hv));
    for (int nc = 0; nc < NCd; nc++) {
        int row = nc * Bd + b;
        for (int l = 0; l < 2; l++)
            for (int d = 0; d < 2; d++) {
                if (which == 0) { g_hbH[0][l][d][row][j] = hv; g_hbL[0][l][d][row][j] = lv; }
                else            g_cS[l][d][row][j] = v;
            }
    }
}

// ---------------- layer0 input projections for all t ----------------
__global__ void k_xproj(const float* __restrict__ emb, const int* __restrict__ cap) {
    __shared__ float xs[32 * Ed];
    __shared__ int toks[32];
    int bm = blockIdx.x, bn = blockIdx.y, d = blockIdx.z;
    int tid = threadIdx.x;
    if (tid < 32) {
        int m = bm * 32 + tid;
        int t = m / Rd, r = m % Rd;
        int nc = r >> 5, b = r & 31;
        toks[tid] = cap[b * (NCd * Td) + nc * Td + t];
    }
    __syncthreads();
    for (int e = tid; e < 32 * Ed; e += 256) {
        int lr = e / Ed, k = e % Ed;
        xs[e] = emb[(long)toks[lr] * Ed + k];
    }
    __syncthreads();
    int tx = tid & 31, ty = tid >> 5;
    float acc[4][4];
#pragma unroll
    for (int a = 0; a < 4; a++)
#pragma unroll
        for (int c = 0; c < 4; c++) acc[a][c] = 0.f;
    int n0 = bn * 128;
    const float* Bp = &g_WihP0[d][0][0];
#pragma unroll 5
    for (int k = 0; k < Ed; k++) {
        float av[4], bv[4];
#pragma unroll
        for (int jr = 0; jr < 4; jr++) av[jr] = xs[(ty + jr * 8) * Ed + k];
#pragma unroll
        for (int jc = 0; jc < 4; jc++) bv[jc] = Bp[(long)k * G4 + n0 + tx + jc * 32];
#pragma unroll
        for (int jr = 0; jr < 4; jr++)
#pragma unroll
            for (int jc = 0; jc < 4; jc++) acc[jr][jc] += av[jr] * bv[jc];
    }
    int m0 = bm * 32;
#pragma unroll
    for (int jr = 0; jr < 4; jr++) {
        int m = m0 + ty + jr * 8;
        int t = m / Rd, r = m % Rd;
#pragma unroll
        for (int jc = 0; jc < 4; jc++) {
            int n = n0 + tx + jc * 32;
            g_X0[d][t][r][n] = acc[jr][jc] + g_bP0[d][n];
        }
    }
}

// =========================================================================
// bf16-split mma.sync GEMM (unchanged from R5).
// mode 0: out[M=3200][Vd] = packed @ Wfc^T + bfc   grid (25, 239, 1)
// mode 1: Z[d][t][r][:] = Y @ W1^T + bP1           grid (Mtiles, 16, 2)
// =========================================================================
__global__ void __launch_bounds__(256, 1)
k_mma(int mode, int w, const float* __restrict__ bfc, float* __restrict__ out) {
    extern __shared__ __align__(16) char dsm[];
    __nv_bfloat16* sA_h = (__nv_bfloat16*)dsm;
    __nv_bfloat16* sA_l = sA_h + 2 * 128 * PITCH;
    __nv_bfloat16* sB_h = sA_l + 2 * 128 * PITCH;
    __nv_bfloat16* sB_l = sB_h + 2 * 128 * PITCH;
    uint32_t uAh = smem_u32(sA_h), uAl = smem_u32(sA_l);
    uint32_t uBh = smem_u32(sB_h), uBl = smem_u32(sB_l);

    int tid = threadIdx.x;
    int lane = tid & 31, wid = tid >> 5;
    int wm = wid >> 1, wn = wid & 1;
    int m0 = blockIdx.x * 128, n0 = blockIdx.y * 128, dz = blockIdx.z;
    int Mtot = mode ? (w + 1) * Rd : Md;

    int sr = tid & 127, kh = tid >> 7;
    int k0 = kh * 16;

    int am = m0 + sr; if (am >= Mtot) am = Mtot - 1;
    int att = 0, arr = 0;
    const __nv_bfloat16 *aH0 = nullptr, *aL0 = nullptr;
    if (mode == 0) { aH0 = &g_packedH[am][0]; aL0 = &g_packedL[am][0]; }
    else { att = am / Rd; arr = am - att * Rd; }

    int bnr = n0 + sr;
    bool bvalid = mode ? true : (bnr < Vd);
    const __nv_bfloat16* BH = mode ? g_W1H : g_WfcH;
    const __nv_bfloat16* BL = mode ? g_W1L : g_WfcL;
    long boff = mode ? ((long)dz * G4 + bnr) * Kfc : (long)bnr * Kfc;

    float c[2][8][4];
#pragma unroll
    for (int mt = 0; mt < 2; mt++)
#pragma unroll
        for (int nt = 0; nt < 8; nt++)
#pragma unroll
            for (int q = 0; q < 4; q++) c[mt][nt][q] = 0.f;

    uint4 vA[4], vB[4];

    auto LOAD = [&](int kc) {
        int kb = kc * 32 + k0;
        if (mode == 0) {
            vA[0] = *(const uint4*)(aH0 + kb);
            vA[1] = *(const uint4*)(aH0 + kb + 8);
            vA[2] = *(const uint4*)(aL0 + kb);
            vA[3] = *(const uint4*)(aL0 + kb + 8);
        } else {
#pragma unroll
            for (int q = 0; q < 2; q++) {
                int kg = kb + q * 8;
                const __nv_bfloat16* pH = (kg < Hd) ? &g_hsH[0][att][arr][kg]
                                                    : &g_hsH[1][w - att][arr][kg - Hd];
                const __nv_bfloat16* pL = (kg < Hd) ? &g_hsL[0][att][arr][kg]
                                                    : &g_hsL[1][w - att][arr][kg - Hd];
                vA[q] = *(const uint4*)pH;
                vA[2 + q] = *(const uint4*)pL;
            }
        }
        if (bvalid) {
            vB[0] = *(const uint4*)(BH + boff + kb);
            vB[1] = *(const uint4*)(BH + boff + kb + 8);
            vB[2] = *(const uint4*)(BL + boff + kb);
            vB[3] = *(const uint4*)(BL + boff + kb + 8);
        } else {
            uint4 z = make_uint4(0, 0, 0, 0);
            vB[0] = z; vB[1] = z; vB[2] = z; vB[3] = z;
        }
    };
    auto STORE = [&](int buf) {
        int base = buf * 128 * PITCH + sr * PITCH + k0;
        *(uint4*)&sA_h[base] = vA[0]; *(uint4*)&sA_h[base + 8] = vA[1];
        *(uint4*)&sA_l[base] = vA[2]; *(uint4*)&sA_l[base + 8] = vA[3];
        *(uint4*)&sB_h[base] = vB[0]; *(uint4*)&sB_h[base + 8] = vB[1];
        *(uint4*)&sB_l[base] = vB[2]; *(uint4*)&sB_l[base + 8] = vB[3];
    };
    auto COMPUTE = [&](int buf) {
        uint32_t bo = (uint32_t)buf * 128 * PITCH * 2;
#pragma unroll
        for (int k16 = 0; k16 < 2; k16++) {
            int ar = lane & 15;
            int acs = k16 * 16 + ((lane >> 4) << 3);
            uint32_t ah[2][4], al[2][4];
#pragma unroll
            for (int mt = 0; mt < 2; mt++) {
                uint32_t off = bo + (uint32_t)((wm * 32 + mt * 16 + ar) * PITCH + acs) * 2;
                LDSM4(ah[mt], uAh + off);
                LDSM4(al[mt], uAl + off);
            }
            int br = (lane & 7) + ((lane >> 4) << 3);
            int bcs = k16 * 16 + (((lane >> 3) & 1) << 3);
            uint32_t bh[8][2], bl[8][2];
#pragma unroll
            for (int ntp = 0; ntp < 4; ntp++) {
                uint32_t off = bo + (uint32_t)((wn * 64 + ntp * 16 + br) * PITCH + bcs) * 2;
                uint32_t r4[4];
                LDSM4(r4, uBh + off);
                bh[ntp * 2][0] = r4[0]; bh[ntp * 2][1] = r4[1];
                bh[ntp * 2 + 1][0] = r4[2]; bh[ntp * 2 + 1][1] = r4[3];
                LDSM4(r4, uBl + off);
                bl[ntp * 2][0] = r4[0]; bl[ntp * 2][1] = r4[1];
                bl[ntp * 2 + 1][0] = r4[2]; bl[ntp * 2 + 1][1] = r4[3];
            }
#pragma unroll
            for (int mt = 0; mt < 2; mt++)
#pragma unroll
                for (int nt = 0; nt < 8; nt++) {
                    MMA16816(c[mt][nt], ah[mt], bh[nt]);
                    MMA16816(c[mt][nt], ah[mt], bl[nt]);
                    MMA16816(c[mt][nt], al[mt], bh[nt]);
                }
        }
    };

    LOAD(0); STORE(0);
    __syncthreads();
    for (int kc = 0; kc < 32; kc++) {
        int buf = kc & 1;
        if (kc < 31) LOAD(kc + 1);
        COMPUTE(buf);
        if (kc < 31) STORE(buf ^ 1);
        __syncthreads();
    }

    int qrow = lane >> 2, qcol = (lane & 3) * 2;
#pragma unroll
    for (int mt = 0; mt < 2; mt++) {
#pragma unroll
        for (int nt = 0; nt < 8; nt++) {
            int n = n0 + wn * 64 + nt * 8 + qcol;
            int mA = m0 + wm * 32 + mt * 16 + qrow;
            if (mode == 0) {
                if (n < Vd) {
                    float2 bb = *(const float2*)&bfc[n];
                    float2 o0 = make_float2(c[mt][nt][0] + bb.x, c[mt][nt][1] + bb.y);
                    float2 o1 = make_float2(c[mt][nt][2] + bb.x, c[mt][nt][3] + bb.y);
                    *(float2*)&out[(long)mA * Vd + n] = o0;
                    *(float2*)&out[(long)(mA + 8) * Vd + n] = o1;
                }
            } else {
                float2 bb = *(const float2*)&g_bP1[dz][n];
                if (mA < Mtot) {
                    int t = mA / Rd, rr = mA - t * Rd;
                    *(float2*)&g_Z[dz][t][rr][n] =
                        make_float2(c[mt][nt][0] + bb.x, c[mt][nt][1] + bb.y);
                }
                if (mA + 8 < Mtot) {
                    int t = (mA + 8) / Rd, rr = (mA + 8) - t * Rd;
                    *(float2*)&g_Z[dz][t][rr][n] =
                        make_float2(c[mt][nt][2] + bb.x, c[mt][nt][3] + bb.y);
                }
            }
        }
    }
}

// =========================================================================
// mma.sync recurrent LSTM step with fused cell epilogue.
// grid (32, 4): blockIdx.x = n-tile (64 gates), blockIdx.y = dir + 2*lay.
// block 320 (10 warps, warp grid 5m x 2n, warp tile 32x32).
// gates = X + h @ Whh^T via 3-term bf16 split; cell in fragment epilogue.
// =========================================================================
__global__ void __launch_bounds__(320, 1)
k_stepm(int p0, int s0, int w0, int act0, int p1, int s1, int w1, int act1) {
    extern __shared__ __align__(16) char dsm[];
    __nv_bfloat16* sA_h = (__nv_bfloat16*)dsm;           // [2][160*PITCH]
    __nv_bfloat16* sA_l = sA_h + 2 * 160 * PITCH;
    __nv_bfloat16* sB_h = sA_l + 2 * 160 * PITCH;        // [2][64*PITCH]
    __nv_bfloat16* sB_l = sB_h + 2 * 64 * PITCH;
    uint32_t uAh = smem_u32(sA_h), uAl = smem_u32(sA_l);
    uint32_t uBh = smem_u32(sB_h), uBl = smem_u32(sB_l);

    int z = blockIdx.y;
    int lay = z >> 1, d = z & 1;
    int act = lay ? act1 : act0;
    if (!act) return;
    int p = lay ? p1 : p0;
    int s = lay ? s1 : s0;
    int w = lay ? w1 : w0;

    int tid = threadIdx.x;
    int lane = tid & 31, wid = tid >> 5;
    int wm = wid >> 1, wn = wid & 1;       // 5(m) x 2(n)
    int n0 = blockIdx.x * 64;

    const __nv_bfloat16* hH = &g_hbH[p][lay][d][0][0];
    const __nv_bfloat16* hL = &g_hbL[p][lay][d][0][0];
    __nv_bfloat16* hoH = &g_hbH[p ^ 1][lay][d][0][0];
    __nv_bfloat16* hoL = &g_hbL[p ^ 1][lay][d][0][0];
    float* cstp = &g_cS[lay][d][0][0];
    int xidx = d ? (w - s) : s;
    const float* Xp = lay ? &g_Z[d][xidx][0][0] : &g_X0[d][xidx][0][0];
    const __nv_bfloat16* BH = &g_WsH[lay][d][0][0];
    const __nv_bfloat16* BL = &g_WsL[lay][d][0][0];

    // staging coords
    int arow = (tid >= 160) ? tid - 160 : tid;   // 0..159
    int ahalf = (tid >= 160) ? 1 : 0;
    int ak0 = ahalf * 16;
    int brow = tid >> 1, bk0 = (tid & 1) * 16;   // tid<128

    float c[2][4][4];
#pragma unroll
    for (int mt = 0; mt < 2; mt++)
#pragma unroll
        for (int nt = 0; nt < 4; nt++)
#pragma unroll
            for (int q = 0; q < 4; q++) c[mt][nt][q] = 0.f;

    uint4 vA[4], vB[4];

    auto LOAD = [&](int kc) {
        int kb = kc * 32;
        int ka = kb + ak0;
        vA[0] = *(const uint4*)(hH + arow * Hd + ka);
        vA[1] = *(const uint4*)(hH + arow * Hd + ka + 8);
        vA[2] = *(const uint4*)(hL + arow * Hd + ka);
        vA[3] = *(const uint4*)(hL + arow * Hd + ka + 8);
        if (tid < 128) {
            long bo = (long)(n0 + brow) * Hd + kb + bk0;
            vB[0] = *(const uint4*)(BH + bo);
            vB[1] = *(const uint4*)(BH + bo + 8);
            vB[2] = *(const uint4*)(BL + bo);
            vB[3] = *(const uint4*)(BL + bo + 8);
        }
    };
    auto STORE = [&](int buf) {
        int sa = buf * 160 * PITCH + arow * PITCH + ak0;
        *(uint4*)&sA_h[sa] = vA[0]; *(uint4*)&sA_h[sa + 8] = vA[1];
        *(uint4*)&sA_l[sa] = vA[2]; *(uint4*)&sA_l[sa + 8] = vA[3];
        if (tid < 128) {
            int sbb = buf * 64 * PITCH + brow * PITCH + bk0;
            *(uint4*)&sB_h[sbb] = vB[0]; *(uint4*)&sB_h[sbb + 8] = vB[1];
            *(uint4*)&sB_l[sbb] = vB[2]; *(uint4*)&sB_l[sbb + 8] = vB[3];
        }
    };
    auto COMPUTE = [&](int buf) {
        uint32_t boA = (uint32_t)buf * 160 * PITCH * 2;
        uint32_t boB = (uint32_t)buf * 64 * PITCH * 2;
#pragma unroll
        for (int k16 = 0; k16 < 2; k16++) {
            int ar = lane & 15;
            int acs = k16 * 16 + ((lane >> 4) << 3);
            uint32_t ah[2][4], al[2][4];
#pragma unroll
            for (int mt = 0; mt < 2; mt++) {
                uint32_t off = boA + (uint32_t)((wm * 32 + mt * 16 + ar) * PITCH + acs) * 2;
                LDSM4(ah[mt], uAh + off);
                LDSM4(al[mt], uAl + off);
            }
            int br = (lane & 7) + ((lane >> 4) << 3);
            int bcs = k16 * 16 + (((lane >> 3) & 1) << 3);
            uint32_t bh[4][2], bl[4][2];
#pragma unroll
            for (int ntp = 0; ntp < 2; ntp++) {
                uint32_t off = boB + (uint32_t)((wn * 32 + ntp * 16 + br) * PITCH + bcs) * 2;
                uint32_t r4[4];
                LDSM4(r4, uBh + off);
                bh[ntp * 2][0] = r4[0]; bh[ntp * 2][1] = r4[1];
                bh[ntp * 2 + 1][0] = r4[2]; bh[ntp * 2 + 1][1] = r4[3];
                LDSM4(r4, uBl + off);
                bl[ntp * 2][0] = r4[0]; bl[ntp * 2][1] = r4[1];
                bl[ntp * 2 + 1][0] = r4[2]; bl[ntp * 2 + 1][1] = r4[3];
            }
#pragma unroll
            for (int mt = 0; mt < 2; mt++)
#pragma unroll
                for (int nt = 0; nt < 4; nt++) {
                    MMA16816(c[mt][nt], ah[mt], bh[nt]);
                    MMA16816(c[mt][nt], ah[mt], bl[nt]);
                    MMA16816(c[mt][nt], al[mt], bh[nt]);
                }
        }
    };

    LOAD(0); STORE(0);
    __syncthreads();
    for (int kc = 0; kc < 16; kc++) {
        int buf = kc & 1;
        if (kc < 15) LOAD(kc + 1);
        COMPUTE(buf);
        if (kc < 15) STORE(buf ^ 1);
        __syncthreads();
    }

    // ---- fused LSTM cell epilogue ----
    // fragment (mt,nt): rows wm*32+mt*16+qrow (+8), cols nbase+quad*2, +1
    // quad 0: (i,f) of h0 | quad 1: (g,o) of h0 | quad 2: (i,f) of h1 | quad 3: (g,o) of h1
    int qrow = lane >> 2, quad = lane & 3;
    bool isIF = (quad & 1) == 0;
#pragma unroll
    for (int mt = 0; mt < 2; mt++) {
#pragma unroll
        for (int nt = 0; nt < 4; nt++) {
            int nbase = n0 + wn * 32 + nt * 8;
            int n = nbase + quad * 2;
            int r1 = wm * 32 + mt * 16 + qrow;
            int r2 = r1 + 8;
            float2 x1 = *(const float2*)&Xp[(long)r1 * G4 + n];
            float2 x2 = *(const float2*)&Xp[(long)r2 * G4 + n];
            float a0 = c[mt][nt][0] + x1.x;
            float a1 = c[mt][nt][1] + x1.y;
            float a2 = c[mt][nt][2] + x2.x;
            float a3 = c[mt][nt][3] + x2.y;
            float b0 = __shfl_xor_sync(0xffffffffu, a0, 1);
            float b1 = __shfl_xor_sync(0xffffffffu, a1, 1);
            float b2 = __shfl_xor_sync(0xffffffffu, a2, 1);
            float b3 = __shfl_xor_sync(0xffffffffu, a3, 1);
            if (isIF) {
                int hh = (nbase >> 2) + (quad >> 1);
#pragma unroll
                for (int rr = 0; rr < 2; rr++) {
                    int row = rr ? r2 : r1;
                    float gi = rr ? a2 : a0;
                    float gf = rr ? a3 : a1;
                    float gg = rr ? b2 : b0;
                    float go = rr ? b3 : b1;
                    float si = 1.f / (1.f + expf(-gi));
                    float sf = 1.f / (1.f + expf(-gf));
                    float so = 1.f / (1.f + expf(-go));
                    float tg = tanhf(gg);
                    float cc = sf * cstp[row * Hd + hh] + si * tg;
                    float h = so * tanhf(cc);
                    cstp[row * Hd + hh] = cc;
                    __nv_bfloat16 hb = __float2bfloat16(h);
                    __nv_bfloat16 lb = __float2bfloat16(h - __bfloat162float(hb));
                    hoH[row * Hd + hh] = hb;
                    hoL[row * Hd + hh] = lb;
                    if (lay == 0) {
                        g_hsH[d][s][row][hh] = hb;
                        g_hsL[d][s][row][hh] = lb;
                    }
                }
            }
        }
    }
}

// ---------------- pack final layer1 states (copy bf16 hi/lo) ----------------
__global__ void k_packst(int w, int pb) {
    int i = blockIdx.x * blockDim.x + threadIdx.x;
    if (i >= Rd * 2 * Hd) return;
    int r = i / (2 * Hd), k = i % (2 * Hd);
    int nc = r >> 5, b = r & 31;
    __nv_bfloat16 hv, lv;
    if (k < Hd) { hv = g_hbH[pb][1][1][r][k]; lv = g_hbL[pb][1][1][r][k]; }
    else        { hv = g_hbH[pb][1][0][r][k - Hd]; lv = g_hbL[pb][1][0][r][k - Hd]; }
    int m = (nc * Td + w) * Bd + b;
    g_packedH[m][k] = hv;
    g_packedL[m][k] = lv;
}

// ---------------- host orchestration ----------------
#define MMA_SMEM  (8 * 128 * PITCH * 2)                       // 81920 bytes
#define STEP_SMEM ((2 * 160 * PITCH * 2 + 2 * 64 * PITCH * 2) * 2)  // 71680 bytes

extern "C" void kernel_launch(void* const* d_in, const int* in_sizes, int n_in,
                              void* d_out, int out_size) {
    const float* img  = (const float*)d_in[0];
    const int*   cap  = (const int*)d_in[1];
    const float* emb  = (const float*)d_in[2];
    const float* Wh   = (const float*)d_in[3];
    const float* bh   = (const float*)d_in[4];
    const float* Wc   = (const float*)d_in[5];
    const float* bc   = (const float*)d_in[6];
    const float* Wih0 = (const float*)d_in[7];
    const float* Whh0 = (const float*)d_in[8];
    const float* bih0 = (const float*)d_in[9];
    const float* bhh0 = (const float*)d_in[10];
    const float* Wih1 = (const float*)d_in[11];
    const float* Whh1 = (const float*)d_in[12];
    const float* bih1 = (const float*)d_in[13];
    const float* bhh1 = (const float*)d_in[14];
    const float* Wfc  = (const float*)d_in[15];
    const float* bfc  = (const float*)d_in[16];
    float* out = (float*)d_out;

    cudaFuncSetAttribute(k_mma, cudaFuncAttributeMaxDynamicSharedMemorySize, MMA_SMEM);
    cudaFuncSetAttribute(k_stepm, cudaFuncAttributeMaxDynamicSharedMemorySize, STEP_SMEM);

    k_pack<<<dim3(4000, 3), 256>>>(Wih0, bih0, bhh0, bih1, bhh1);
    k_packbf<<<dim3(122088, 3), 256>>>(Wfc, Wih1, Whh0, Whh1);
    k_init<<<(2 * Bd * Hd + 255) / 256, 256>>>(img, Wh, bh, Wc, bc);
    k_xproj<<<dim3(100, 16, 2), 256>>>(emb, cap);

    int p0 = 0, p1 = 0;
    // prelude: layer0 of word 0 (single step), then Z(0)
    k_stepm<<<dim3(32, 4), 320, STEP_SMEM>>>(p0, 0, 0, 1, p1, 0, 0, 0);
    p0 ^= 1;
    k_mma<<<dim3(2, 16, 2), 256, MMA_SMEM>>>(1, 0, nullptr, nullptr);

    for (int w = 0; w < Td; w++) {
        int s0max = (w + 1 < Td) ? (w + 1) : -1;   // layer0 word w+1 steps
        int s1max = w;                              // layer1 word w steps
        int smax = s0max > s1max ? s0max : s1max;
        for (int s = 0; s <= smax; s++) {
            int a0 = (s <= s0max) ? 1 : 0;
            int a1 = (s <= s1max) ? 1 : 0;
            k_stepm<<<dim3(32, 4), 320, STEP_SMEM>>>(p0, s, w + 1, a0, p1, s, w, a1);
            if (a0) p0 ^= 1;
            if (a1) p1 ^= 1;
        }
        k_packst<<<(Rd * 2 * Hd + 255) / 256, 256>>>(w, p1);
        if (w + 1 < Td) {
            int Mt = ((w + 2) * Rd + 127) / 128;
            k_mma<<<dim3(Mt, 16, 2), 256, MMA_SMEM>>>(1, w + 1, nullptr, nullptr);
        }
    }
    k_mma<<<dim3(25, 239, 1), 256, MMA_SMEM>>>(0, 0, bfc, out);
}

// round 7
// speedup vs baseline: 3.3251x; 1.0002x over previous
#include <cuda_runtime.h>
#include <cuda_bf16.h>
#include <math.h>
#include <stdint.h>

// Problem constants
#define Hd   512
#define G4   2048      // 4*H
#define Ed   250
#define Bd   32
#define NCd  5
#define Td   20
#define Rd   160       // NC*B
#define Vd   30522
#define CNNd 2048
#define Md   3200      // NC*T*B
#define Kfc  1024      // 2*H
#define PITCH 40       // smem row pitch in bf16 elems (80B, bank-conflict-free)

// ---------------- device scratch (no allocations allowed) ----------------
__device__ float g_WihP0[2][Ed][G4];
__device__ float g_bP0[2][G4];
__device__ float g_bP1[2][G4];
__device__ float g_X0[2][Td][Rd][G4];        // layer0 input projections (+bias)
__device__ float g_Z[2][Td][Rd][G4];         // layer1 input projections (+bias)
__device__ float g_cS[2][2][Rd][Hd];         // [layer][dir][row][h]  fp32 cell state
// LSTM h state as bf16 hi/lo, double buffered: [parity][layer][dir][row][h]
__device__ __nv_bfloat16 g_hbH[2][2][2][Rd][Hd];
__device__ __nv_bfloat16 g_hbL[2][2][2][Rd][Hd];
// bf16 hi/lo split activations (A operands for mma GEMMs)
__device__ __nv_bfloat16 g_hsH[2][Td][Rd][Hd];
__device__ __nv_bfloat16 g_hsL[2][Td][Rd][Hd];
__device__ __nv_bfloat16 g_packedH[Md][Kfc];
__device__ __nv_bfloat16 g_packedL[Md][Kfc];
// bf16 hi/lo split weights (B operands, K-major rows)
__device__ __nv_bfloat16 g_WfcH[(long)Vd * Kfc];
__device__ __nv_bfloat16 g_WfcL[(long)Vd * Kfc];
__device__ __nv_bfloat16 g_W1H[2L * G4 * Kfc];   // gate-interleaved [d][n][k]
__device__ __nv_bfloat16 g_W1L[2L * G4 * Kfc];
__device__ __nv_bfloat16 g_WsH[2][2][G4][Hd];    // recurrent weights [lay][d][n][k]
__device__ __nv_bfloat16 g_WsL[2][2][G4][Hd];

__device__ __forceinline__ uint32_t smem_u32(const void* p) {
    uint32_t a;
    asm("{ .reg .u64 t; cvta.to.shared.u64 t, %1; cvt.u32.u64 %0, t; }"
        : "=r"(a) : "l"(p));
    return a;
}
#define LDSM4(r, addr) \
    asm volatile("ldmatrix.sync.aligned.m8n8.x4.shared.b16 {%0,%1,%2,%3}, [%4];" \
        : "=r"((r)[0]), "=r"((r)[1]), "=r"((r)[2]), "=r"((r)[3]) : "r"(addr))
#define MMA16816(c, a, b) \
    asm volatile("mma.sync.aligned.m16n8k16.row.col.f32.bf16.bf16.f32 " \
        "{%0,%1,%2,%3}, {%4,%5,%6,%7}, {%8,%9}, {%0,%1,%2,%3};" \
        : "+f"((c)[0]), "+f"((c)[1]), "+f"((c)[2]), "+f"((c)[3]) \
        : "r"((a)[0]), "r"((a)[1]), "r"((a)[2]), "r"((a)[3]), "r"((b)[0]), "r"((b)[1]))

// ---------------- weight packing (fp32 for xproj, biases) ----------------
__global__ void k_pack(const float* __restrict__ Wih0,
                       const float* __restrict__ bih0, const float* __restrict__ bhh0,
                       const float* __restrict__ bih1, const float* __restrict__ bhh1) {
    int region = blockIdx.y;
    long i = (long)blockIdx.x * blockDim.x + threadIdx.x;
    if (region == 0) {
        if (i >= 2L * Ed * G4) return;
        int d = (int)(i / (Ed * G4)); int rem = (int)(i % (Ed * G4));
        int k = rem / G4, n = rem % G4;
        int h = n >> 2, g = n & 3;
        g_WihP0[d][k][n] = Wih0[((long)d * G4 + g * Hd + h) * Ed + k];
    } else if (region == 1) {
        if (i >= 2L * G4) return;
        int d = (int)(i / G4); int n = (int)(i % G4);
        int h = n >> 2, g = n & 3;
        long j = (long)d * G4 + g * Hd + h;
        g_bP0[d][n] = bih0[j] + bhh0[j];
    } else {
        if (i >= 2L * G4) return;
        int d = (int)(i / G4); int n = (int)(i % G4);
        int h = n >> 2, g = n & 3;
        long j = (long)d * G4 + g * Hd + h;
        g_bP1[d][n] = bih1[j] + bhh1[j];
    }
}

// ---------------- bf16 hi/lo split packing for tensor-core GEMMs ----------------
__global__ void k_packbf(const float* __restrict__ Wfc, const float* __restrict__ Wih1,
                         const float* __restrict__ Whh0, const float* __restrict__ Whh1) {
    long i = (long)blockIdx.x * blockDim.x + threadIdx.x;
    if (blockIdx.y == 0) {
        if (i >= (long)Vd * Kfc) return;
        float x = Wfc[i];
        __nv_bfloat16 h = __float2bfloat16(x);
        g_WfcH[i] = h;
        g_WfcL[i] = __float2bfloat16(x - __bfloat162float(h));
    } else if (blockIdx.y == 1) {
        if (i >= 2L * G4 * Kfc) return;
        int d = (int)(i / (G4 * Kfc)); long rem = i % ((long)G4 * Kfc);
        int n = (int)(rem / Kfc), k = (int)(rem % Kfc);
        int h = n >> 2, g = n & 3;
        float x = Wih1[((long)d * G4 + g * Hd + h) * Kfc + k];
        __nv_bfloat16 hb = __float2bfloat16(x);
        g_W1H[i] = hb;
        g_W1L[i] = __float2bfloat16(x - __bfloat162float(hb));
    } else {
        if (i >= 2L * 2 * G4 * Hd) return;
        int lay = (int)(i / (2L * G4 * Hd));
        long rem = i % (2L * G4 * Hd);
        int d = (int)(rem / ((long)G4 * Hd));
        long r2 = rem % ((long)G4 * Hd);
        int n = (int)(r2 / Hd), k = (int)(r2 % Hd);
        int h = n >> 2, g = n & 3;
        const float* W = lay ? Whh1 : Whh0;
        float x = W[((long)d * G4 + g * Hd + h) * Hd + k];
        __nv_bfloat16 hb = __float2bfloat16(x);
        g_WsH[lay][d][n][k] = hb;
        g_WsL[lay][d][n][k] = __float2bfloat16(x - __bfloat162float(hb));
    }
}

// ---------------- initial states: bf16 hi/lo h0, fp32 c0 ----------------
__global__ void k_init(const float* __restrict__ img, const float* __restrict__ Wh,
                       const float* __restrict__ bh, const float* __restrict__ Wc,
                       const float* __restrict__ bc) {
    int i = blockIdx.x * blockDim.x + threadIdx.x;
    if (i >= 2 * Bd * Hd) return;
    int which = i / (Bd * Hd);
    int rem = i % (Bd * Hd);
    int b = rem / Hd, j = rem % Hd;
    const float* W = which ? Wc : Wh;
    const float* bias = which ? bc : bh;
    const float4* a4 = (const float4*)(img + (long)b * CNNd);
    const float4* w4 = (const float4*)(W + (long)j * CNNd);
    float acc = 0.f;
#pragma unroll 4
    for (int k = 0; k < CNNd / 4; k++) {
        float4 a = a4[k], w = w4[k];
        acc += a.x * w.x + a.y * w.y + a.z * w.z + a.w * w.w;
    }
    float v = fmaxf(acc + bias[j], 0.f);
    __nv_bfloat16 hv = __float2bfloat16(v);
    __nv_bfloat16 lv = __float2bfloat16(v - __bfloat162float(hv));
    for (int nc = 0; nc < NCd; nc++) {
        int row = nc * Bd + b;
        for (int l = 0; l < 2; l++)
            for (int d = 0; d < 2; d++) {
                if (which == 0) { g_hbH[0][l][d][row][j] = hv; g_hbL[0][l][d][row][j] = lv; }
                else            g_cS[l][d][row][j] = v;
            }
    }
}

// ---------------- layer0 input projections for all t ----------------
__global__ void k_xproj(const float* __restrict__ emb, const int* __restrict__ cap) {
    __shared__ float xs[32 * Ed];
    __shared__ int toks[32];
    int bm = blockIdx.x, bn = blockIdx.y, d = blockIdx.z;
    int tid = threadIdx.x;
    if (tid < 32) {
        int m = bm * 32 + tid;
        int t = m / Rd, r = m % Rd;
        int nc = r >> 5, b = r & 31;
        toks[tid] = cap[b * (NCd * Td) + nc * Td + t];
    }
    __syncthreads();
    for (int e = tid; e < 32 * Ed; e += 256) {
        int lr = e / Ed, k = e % Ed;
        xs[e] = emb[(long)toks[lr] * Ed + k];
    }
    __syncthreads();
    int tx = tid & 31, ty = tid >> 5;
    float acc[4][4];
#pragma unroll
    for (int a = 0; a < 4; a++)
#pragma unroll
        for (int c = 0; c < 4; c++) acc[a][c] = 0.f;
    int n0 = bn * 128;
    const float* Bp = &g_WihP0[d][0][0];
#pragma unroll 5
    for (int k = 0; k < Ed; k++) {
        float av[4], bv[4];
#pragma unroll
        for (int jr = 0; jr < 4; jr++) av[jr] = xs[(ty + jr * 8) * Ed + k];
#pragma unroll
        for (int jc = 0; jc < 4; jc++) bv[jc] = Bp[(long)k * G4 + n0 + tx + jc * 32];
#pragma unroll
        for (int jr = 0; jr < 4; jr++)
#pragma unroll
            for (int jc = 0; jc < 4; jc++) acc[jr][jc] += av[jr] * bv[jc];
    }
    int m0 = bm * 32;
#pragma unroll
    for (int jr = 0; jr < 4; jr++) {
        int m = m0 + ty + jr * 8;
        int t = m / Rd, r = m % Rd;
#pragma unroll
        for (int jc = 0; jc < 4; jc++) {
            int n = n0 + tx + jc * 32;
            g_X0[d][t][r][n] = acc[jr][jc] + g_bP0[d][n];
        }
    }
}

// =========================================================================
// bf16-split mma.sync GEMM (unchanged from R5).
// mode 0: out[M=3200][Vd] = packed @ Wfc^T + bfc   grid (25, 239, 1)
// mode 1: Z[d][t][r][:] = Y @ W1^T + bP1           grid (Mtiles, 16, 2)
// =========================================================================
__global__ void __launch_bounds__(256, 1)
k_mma(int mode, int w, const float* __restrict__ bfc, float* __restrict__ out) {
    extern __shared__ __align__(16) char dsm[];
    __nv_bfloat16* sA_h = (__nv_bfloat16*)dsm;
    __nv_bfloat16* sA_l = sA_h + 2 * 128 * PITCH;
    __nv_bfloat16* sB_h = sA_l + 2 * 128 * PITCH;
    __nv_bfloat16* sB_l = sB_h + 2 * 128 * PITCH;
    uint32_t uAh = smem_u32(sA_h), uAl = smem_u32(sA_l);
    uint32_t uBh = smem_u32(sB_h), uBl = smem_u32(sB_l);

    int tid = threadIdx.x;
    int lane = tid & 31, wid = tid >> 5;
    int wm = wid >> 1, wn = wid & 1;
    int m0 = blockIdx.x * 128, n0 = blockIdx.y * 128, dz = blockIdx.z;
    int Mtot = mode ? (w + 1) * Rd : Md;

    int sr = tid & 127, kh = tid >> 7;
    int k0 = kh * 16;

    int am = m0 + sr; if (am >= Mtot) am = Mtot - 1;
    int att = 0, arr = 0;
    const __nv_bfloat16 *aH0 = nullptr, *aL0 = nullptr;
    if (mode == 0) { aH0 = &g_packedH[am][0]; aL0 = &g_packedL[am][0]; }
    else { att = am / Rd; arr = am - att * Rd; }

    int bnr = n0 + sr;
    bool bvalid = mode ? true : (bnr < Vd);
    const __nv_bfloat16* BH = mode ? g_W1H : g_WfcH;
    const __nv_bfloat16* BL = mode ? g_W1L : g_WfcL;
    long boff = mode ? ((long)dz * G4 + bnr) * Kfc : (long)bnr * Kfc;

    float c[2][8][4];
#pragma unroll
    for (int mt = 0; mt < 2; mt++)
#pragma unroll
        for (int nt = 0; nt < 8; nt++)
#pragma unroll
            for (int q = 0; q < 4; q++) c[mt][nt][q] = 0.f;

    uint4 vA[4], vB[4];

    auto LOAD = [&](int kc) {
        int kb = kc * 32 + k0;
        if (mode == 0) {
            vA[0] = *(const uint4*)(aH0 + kb);
            vA[1] = *(const uint4*)(aH0 + kb + 8);
            vA[2] = *(const uint4*)(aL0 + kb);
            vA[3] = *(const uint4*)(aL0 + kb + 8);
        } else {
#pragma unroll
            for (int q = 0; q < 2; q++) {
                int kg = kb + q * 8;
                const __nv_bfloat16* pH = (kg < Hd) ? &g_hsH[0][att][arr][kg]
                                                    : &g_hsH[1][w - att][arr][kg - Hd];
                const __nv_bfloat16* pL = (kg < Hd) ? &g_hsL[0][att][arr][kg]
                                                    : &g_hsL[1][w - att][arr][kg - Hd];
                vA[q] = *(const uint4*)pH;
                vA[2 + q] = *(const uint4*)pL;
            }
        }
        if (bvalid) {
            vB[0] = *(const uint4*)(BH + boff + kb);
            vB[1] = *(const uint4*)(BH + boff + kb + 8);
            vB[2] = *(const uint4*)(BL + boff + kb);
            vB[3] = *(const uint4*)(BL + boff + kb + 8);
        } else {
            uint4 z = make_uint4(0, 0, 0, 0);
            vB[0] = z; vB[1] = z; vB[2] = z; vB[3] = z;
        }
    };
    auto STORE = [&](int buf) {
        int base = buf * 128 * PITCH + sr * PITCH + k0;
        *(uint4*)&sA_h[base] = vA[0]; *(uint4*)&sA_h[base + 8] = vA[1];
        *(uint4*)&sA_l[base] = vA[2]; *(uint4*)&sA_l[base + 8] = vA[3];
        *(uint4*)&sB_h[base] = vB[0]; *(uint4*)&sB_h[base + 8] = vB[1];
        *(uint4*)&sB_l[base] = vB[2]; *(uint4*)&sB_l[base + 8] = vB[3];
    };
    auto COMPUTE = [&](int buf) {
        uint32_t bo = (uint32_t)buf * 128 * PITCH * 2;
#pragma unroll
        for (int k16 = 0; k16 < 2; k16++) {
            int ar = lane & 15;
            int acs = k16 * 16 + ((lane >> 4) << 3);
            uint32_t ah[2][4], al[2][4];
#pragma unroll
            for (int mt = 0; mt < 2; mt++) {
                uint32_t off = bo + (uint32_t)((wm * 32 + mt * 16 + ar) * PITCH + acs) * 2;
                LDSM4(ah[mt], uAh + off);
                LDSM4(al[mt], uAl + off);
            }
            int br = (lane & 7) + ((lane >> 4) << 3);
            int bcs = k16 * 16 + (((lane >> 3) & 1) << 3);
            uint32_t bh[8][2], bl[8][2];
#pragma unroll
            for (int ntp = 0; ntp < 4; ntp++) {
                uint32_t off = bo + (uint32_t)((wn * 64 + ntp * 16 + br) * PITCH + bcs) * 2;
                uint32_t r4[4];
                LDSM4(r4, uBh + off);
                bh[ntp * 2][0] = r4[0]; bh[ntp * 2][1] = r4[1];
                bh[ntp * 2 + 1][0] = r4[2]; bh[ntp * 2 + 1][1] = r4[3];
                LDSM4(r4, uBl + off);
                bl[ntp * 2][0] = r4[0]; bl[ntp * 2][1] = r4[1];
                bl[ntp * 2 + 1][0] = r4[2]; bl[ntp * 2 + 1][1] = r4[3];
            }
#pragma unroll
            for (int mt = 0; mt < 2; mt++)
#pragma unroll
                for (int nt = 0; nt < 8; nt++) {
                    MMA16816(c[mt][nt], ah[mt], bh[nt]);
                    MMA16816(c[mt][nt], ah[mt], bl[nt]);
                    MMA16816(c[mt][nt], al[mt], bh[nt]);
                }
        }
    };

    LOAD(0); STORE(0);
    __syncthreads();
    for (int kc = 0; kc < 32; kc++) {
        int buf = kc & 1;
        if (kc < 31) LOAD(kc + 1);
        COMPUTE(buf);
        if (kc < 31) STORE(buf ^ 1);
        __syncthreads();
    }

    int qrow = lane >> 2, qcol = (lane & 3) * 2;
#pragma unroll
    for (int mt = 0; mt < 2; mt++) {
#pragma unroll
        for (int nt = 0; nt < 8; nt++) {
            int n = n0 + wn * 64 + nt * 8 + qcol;
            int mA = m0 + wm * 32 + mt * 16 + qrow;
            if (mode == 0) {
                if (n < Vd) {
                    float2 bb = *(const float2*)&bfc[n];
                    float2 o0 = make_float2(c[mt][nt][0] + bb.x, c[mt][nt][1] + bb.y);
                    float2 o1 = make_float2(c[mt][nt][2] + bb.x, c[mt][nt][3] + bb.y);
                    *(float2*)&out[(long)mA * Vd + n] = o0;
                    *(float2*)&out[(long)(mA + 8) * Vd + n] = o1;
                }
            } else {
                float2 bb = *(const float2*)&g_bP1[dz][n];
                if (mA < Mtot) {
                    int t = mA / Rd, rr = mA - t * Rd;
                    *(float2*)&g_Z[dz][t][rr][n] =
                        make_float2(c[mt][nt][0] + bb.x, c[mt][nt][1] + bb.y);
                }
                if (mA + 8 < Mtot) {
                    int t = (mA + 8) / Rd, rr = (mA + 8) - t * Rd;
                    *(float2*)&g_Z[dz][t][rr][n] =
                        make_float2(c[mt][nt][2] + bb.x, c[mt][nt][3] + bb.y);
                }
            }
        }
    }
}

// =========================================================================
// mma.sync recurrent LSTM step with fused cell epilogue.
// grid (32, 4): blockIdx.x = n-tile (64 gates), blockIdx.y = dir + 2*lay.
// block 320 (10 warps, warp grid 5m x 2n, warp tile 32x32).
// gates = X + h @ Whh^T via 3-term bf16 split; cell in fragment epilogue.
// =========================================================================
__global__ void __launch_bounds__(320, 1)
k_stepm(int p0, int s0, int w0, int act0, int p1, int s1, int w1, int act1) {
    extern __shared__ __align__(16) char dsm[];
    __nv_bfloat16* sA_h = (__nv_bfloat16*)dsm;           // [2][160*PITCH]
    __nv_bfloat16* sA_l = sA_h + 2 * 160 * PITCH;
    __nv_bfloat16* sB_h = sA_l + 2 * 160 * PITCH;        // [2][64*PITCH]
    __nv_bfloat16* sB_l = sB_h + 2 * 64 * PITCH;
    uint32_t uAh = smem_u32(sA_h), uAl = smem_u32(sA_l);
    uint32_t uBh = smem_u32(sB_h), uBl = smem_u32(sB_l);

    int z = blockIdx.y;
    int lay = z >> 1, d = z & 1;
    int act = lay ? act1 : act0;
    if (!act) return;
    int p = lay ? p1 : p0;
    int s = lay ? s1 : s0;
    int w = lay ? w1 : w0;

    int tid = threadIdx.x;
    int lane = tid & 31, wid = tid >> 5;
    int wm = wid >> 1, wn = wid & 1;       // 5(m) x 2(n)
    int n0 = blockIdx.x * 64;

    const __nv_bfloat16* hH = &g_hbH[p][lay][d][0][0];
    const __nv_bfloat16* hL = &g_hbL[p][lay][d][0][0];
    __nv_bfloat16* hoH = &g_hbH[p ^ 1][lay][d][0][0];
    __nv_bfloat16* hoL = &g_hbL[p ^ 1][lay][d][0][0];
    float* cstp = &g_cS[lay][d][0][0];
    int xidx = d ? (w - s) : s;
    const float* Xp = lay ? &g_Z[d][xidx][0][0] : &g_X0[d][xidx][0][0];
    const __nv_bfloat16* BH = &g_WsH[lay][d][0][0];
    const __nv_bfloat16* BL = &g_WsL[lay][d][0][0];

    // staging coords
    int arow = (tid >= 160) ? tid - 160 : tid;   // 0..159
    int ahalf = (tid >= 160) ? 1 : 0;
    int ak0 = ahalf * 16;
    int brow = tid >> 1, bk0 = (tid & 1) * 16;   // tid<128

    float c[2][4][4];
#pragma unroll
    for (int mt = 0; mt < 2; mt++)
#pragma unroll
        for (int nt = 0; nt < 4; nt++)
#pragma unroll
            for (int q = 0; q < 4; q++) c[mt][nt][q] = 0.f;

    uint4 vA[4], vB[4];

    auto LOAD = [&](int kc) {
        int kb = kc * 32;
        int ka = kb + ak0;
        vA[0] = *(const uint4*)(hH + arow * Hd + ka);
        vA[1] = *(const uint4*)(hH + arow * Hd + ka + 8);
        vA[2] = *(const uint4*)(hL + arow * Hd + ka);
        vA[3] = *(const uint4*)(hL + arow * Hd + ka + 8);
        if (tid < 128) {
            long bo = (long)(n0 + brow) * Hd + kb + bk0;
            vB[0] = *(const uint4*)(BH + bo);
            vB[1] = *(const uint4*)(BH + bo + 8);
            vB[2] = *(const uint4*)(BL + bo);
            vB[3] = *(const uint4*)(BL + bo + 8);
        }
    };
    auto STORE = [&](int buf) {
        int sa = buf * 160 * PITCH + arow * PITCH + ak0;
        *(uint4*)&sA_h[sa] = vA[0]; *(uint4*)&sA_h[sa + 8] = vA[1];
        *(uint4*)&sA_l[sa] = vA[2]; *(uint4*)&sA_l[sa + 8] = vA[3];
        if (tid < 128) {
            int sbb = buf * 64 * PITCH + brow * PITCH + bk0;
            *(uint4*)&sB_h[sbb] = vB[0]; *(uint4*)&sB_h[sbb + 8] = vB[1];
            *(uint4*)&sB_l[sbb] = vB[2]; *(uint4*)&sB_l[sbb + 8] = vB[3];
        }
    };
    auto COMPUTE = [&](int buf) {
        uint32_t boA = (uint32_t)buf * 160 * PITCH * 2;
        uint32_t boB = (uint32_t)buf * 64 * PITCH * 2;
#pragma unroll
        for (int k16 = 0; k16 < 2; k16++) {
            int ar = lane & 15;
            int acs = k16 * 16 + ((lane >> 4) << 3);
            uint32_t ah[2][4], al[2][4];
#pragma unroll
            for (int mt = 0; mt < 2; mt++) {
                uint32_t off = boA + (uint32_t)((wm * 32 + mt * 16 + ar) * PITCH + acs) * 2;
                LDSM4(ah[mt], uAh + off);
                LDSM4(al[mt], uAl + off);
            }
            int br = (lane & 7) + ((lane >> 4) << 3);
            int bcs = k16 * 16 + (((lane >> 3) & 1) << 3);
            uint32_t bh[4][2], bl[4][2];
#pragma unroll
            for (int ntp = 0; ntp < 2; ntp++) {
                uint32_t off = boB + (uint32_t)((wn * 32 + ntp * 16 + br) * PITCH + bcs) * 2;
                uint32_t r4[4];
                LDSM4(r4, uBh + off);
                bh[ntp * 2][0] = r4[0]; bh[ntp * 2][1] = r4[1];
                bh[ntp * 2 + 1][0] = r4[2]; bh[ntp * 2 + 1][1] = r4[3];
                LDSM4(r4, uBl + off);
                bl[ntp * 2][0] = r4[0]; bl[ntp * 2][1] = r4[1];
                bl[ntp * 2 + 1][0] = r4[2]; bl[ntp * 2 + 1][1] = r4[3];
            }
#pragma unroll
            for (int mt = 0; mt < 2; mt++)
#pragma unroll
                for (int nt = 0; nt < 4; nt++) {
                    MMA16816(c[mt][nt], ah[mt], bh[nt]);
                    MMA16816(c[mt][nt], ah[mt], bl[nt]);
                    MMA16816(c[mt][nt], al[mt], bh[nt]);
                }
        }
    };

    LOAD(0); STORE(0);
    __syncthreads();
    for (int kc = 0; kc < 16; kc++) {
        int buf = kc & 1;
        if (kc < 15) LOAD(kc + 1);
        COMPUTE(buf);
        if (kc < 15) STORE(buf ^ 1);
        __syncthreads();
    }

    // ---- fused LSTM cell epilogue ----
    // fragment (mt,nt): rows wm*32+mt*16+qrow (+8), cols nbase+quad*2, +1
    // quad 0: (i,f) of h0 | quad 1: (g,o) of h0 | quad 2: (i,f) of h1 | quad 3: (g,o) of h1
    int qrow = lane >> 2, quad = lane & 3;
    bool isIF = (quad & 1) == 0;
#pragma unroll
    for (int mt = 0; mt < 2; mt++) {
#pragma unroll
        for (int nt = 0; nt < 4; nt++) {
            int nbase = n0 + wn * 32 + nt * 8;
            int n = nbase + quad * 2;
            int r1 = wm * 32 + mt * 16 + qrow;
            int r2 = r1 + 8;
            float2 x1 = *(const float2*)&Xp[(long)r1 * G4 + n];
            float2 x2 = *(const float2*)&Xp[(long)r2 * G4 + n];
            float a0 = c[mt][nt][0] + x1.x;
            float a1 = c[mt][nt][1] + x1.y;
            float a2 = c[mt][nt][2] + x2.x;
            float a3 = c[mt][nt][3] + x2.y;
            float b0 = __shfl_xor_sync(0xffffffffu, a0, 1);
            float b1 = __shfl_xor_sync(0xffffffffu, a1, 1);
            float b2 = __shfl_xor_sync(0xffffffffu, a2, 1);
            float b3 = __shfl_xor_sync(0xffffffffu, a3, 1);
            if (isIF) {
                int hh = (nbase >> 2) + (quad >> 1);
#pragma unroll
                for (int rr = 0; rr < 2; rr++) {
                    int row = rr ? r2 : r1;
                    float gi = rr ? a2 : a0;
                    float gf = rr ? a3 : a1;
                    float gg = rr ? b2 : b0;
                    float go = rr ? b3 : b1;
                    float si = 1.f / (1.f + expf(-gi));
                    float sf = 1.f / (1.f + expf(-gf));
                    float so = 1.f / (1.f + expf(-go));
                    float tg = tanhf(gg);
                    float cc = sf * cstp[row * Hd + hh] + si * tg;
                    float h = so * tanhf(cc);
                    cstp[row * Hd + hh] = cc;
                    __nv_bfloat16 hb = __float2bfloat16(h);
                    __nv_bfloat16 lb = __float2bfloat16(h - __bfloat162float(hb));
                    hoH[row * Hd + hh] = hb;
                    hoL[row * Hd + hh] = lb;
                    if (lay == 0) {
                        g_hsH[d][s][row][hh] = hb;
                        g_hsL[d][s][row][hh] = lb;
                    }
                }
            }
        }
    }
}

// ---------------- pack final layer1 states (copy bf16 hi/lo) ----------------
__global__ void k_packst(int w, int pb) {
    int i = blockIdx.x * blockDim.x + threadIdx.x;
    if (i >= Rd * 2 * Hd) return;
    int r = i / (2 * Hd), k = i % (2 * Hd);
    int nc = r >> 5, b = r & 31;
    __nv_bfloat16 hv, lv;
    if (k < Hd) { hv = g_hbH[pb][1][1][r][k]; lv = g_hbL[pb][1][1][r][k]; }
    else        { hv = g_hbH[pb][1][0][r][k - Hd]; lv = g_hbL[pb][1][0][r][k - Hd]; }
    int m = (nc * Td + w) * Bd + b;
    g_packedH[m][k] = hv;
    g_packedL[m][k] = lv;
}

// ---------------- host orchestration ----------------
#define MMA_SMEM  (8 * 128 * PITCH * 2)                       // 81920 bytes
#define STEP_SMEM ((2 * 160 * PITCH * 2 + 2 * 64 * PITCH * 2) * 2)  // 71680 bytes

extern "C" void kernel_launch(void* const* d_in, const int* in_sizes, int n_in,
                              void* d_out, int out_size) {
    const float* img  = (const float*)d_in[0];
    const int*   cap  = (const int*)d_in[1];
    const float* emb  = (const float*)d_in[2];
    const float* Wh   = (const float*)d_in[3];
    const float* bh   = (const float*)d_in[4];
    const float* Wc   = (const float*)d_in[5];
    const float* bc   = (const float*)d_in[6];
    const float* Wih0 = (const float*)d_in[7];
    const float* Whh0 = (const float*)d_in[8];
    const float* bih0 = (const float*)d_in[9];
    const float* bhh0 = (const float*)d_in[10];
    const float* Wih1 = (const float*)d_in[11];
    const float* Whh1 = (const float*)d_in[12];
    const float* bih1 = (const float*)d_in[13];
    const float* bhh1 = (const float*)d_in[14];
    const float* Wfc  = (const float*)d_in[15];
    const float* bfc  = (const float*)d_in[16];
    float* out = (float*)d_out;

    cudaFuncSetAttribute(k_mma, cudaFuncAttributeMaxDynamicSharedMemorySize, MMA_SMEM);
    cudaFuncSetAttribute(k_stepm, cudaFuncAttributeMaxDynamicSharedMemorySize, STEP_SMEM);

    k_pack<<<dim3(4000, 3), 256>>>(Wih0, bih0, bhh0, bih1, bhh1);
    k_packbf<<<dim3(122088, 3), 256>>>(Wfc, Wih1, Whh0, Whh1);
    k_init<<<(2 * Bd * Hd + 255) / 256, 256>>>(img, Wh, bh, Wc, bc);
    k_xproj<<<dim3(100, 16, 2), 256>>>(emb, cap);

    int p0 = 0, p1 = 0;
    // prelude: layer0 of word 0 (single step), then Z(0)
    k_stepm<<<dim3(32, 4), 320, STEP_SMEM>>>(p0, 0, 0, 1, p1, 0, 0, 0);
    p0 ^= 1;
    k_mma<<<dim3(2, 16, 2), 256, MMA_SMEM>>>(1, 0, nullptr, nullptr);

    for (int w = 0; w < Td; w++) {
        int s0max = (w + 1 < Td) ? (w + 1) : -1;   // layer0 word w+1 steps
        int s1max = w;                              // layer1 word w steps
        int smax = s0max > s1max ? s0max : s1max;
        for (int s = 0; s <= smax; s++) {
            int a0 = (s <= s0max) ? 1 : 0;
            int a1 = (s <= s1max) ? 1 : 0;
            k_stepm<<<dim3(32, 4), 320, STEP_SMEM>>>(p0, s, w + 1, a0, p1, s, w, a1);
            if (a0) p0 ^= 1;
            if (a1) p1 ^= 1;
        }
        k_packst<<<(Rd * 2 * Hd + 255) / 256, 256>>>(w, p1);
        if (w + 1 < Td) {
            int Mt = ((w + 2) * Rd + 127) / 128;
            k_mma<<<dim3(Mt, 16, 2), 256, MMA_SMEM>>>(1, w + 1, nullptr, nullptr);
        }
    }
    k_mma<<<dim3(25, 239, 1), 256, MMA_SMEM>>>(0, 0, bfc, out);
}

// round 8
// speedup vs baseline: 3.3296x; 1.0013x over previous
#include <cuda_runtime.h>
#include <cuda_bf16.h>
#include <math.h>
#include <stdint.h>

// Problem constants
#define Hd   512
#define G4   2048      // 4*H
#define Ed   250
#define Bd   32
#define NCd  5
#define Td   20
#define Rd   160       // NC*B
#define Vd   30522
#define CNNd 2048
#define Md   3200      // NC*T*B
#define Kfc  1024      // 2*H
#define PITCH 40       // smem row pitch in bf16 elems (80B, bank-conflict-free)

// ---------------- device scratch (no allocations allowed) ----------------
__device__ float g_WihP0[2][Ed][G4];
__device__ float g_bP0[2][G4];
__device__ float g_bP1[2][G4];
__device__ float g_X0[2][Td][Rd][G4];        // layer0 input projections (+bias)
__device__ float g_Z[2][Td][Rd][G4];         // layer1 input projections (+bias)
__device__ float g_cS[2][2][Rd][Hd];         // [layer][dir][row][h]  fp32 cell state
// LSTM h state as bf16 hi/lo, double buffered: [parity][layer][dir][row][h]
__device__ __nv_bfloat16 g_hbH[2][2][2][Rd][Hd];
__device__ __nv_bfloat16 g_hbL[2][2][2][Rd][Hd];
// bf16 hi/lo split activations (A operands for mma GEMMs)
__device__ __nv_bfloat16 g_hsH[2][Td][Rd][Hd];
__device__ __nv_bfloat16 g_hsL[2][Td][Rd][Hd];
__device__ __nv_bfloat16 g_packedH[Md][Kfc];
__device__ __nv_bfloat16 g_packedL[Md][Kfc];
// bf16 hi/lo split weights (B operands, K-major rows)
__device__ __nv_bfloat16 g_WfcH[(long)Vd * Kfc];
__device__ __nv_bfloat16 g_WfcL[(long)Vd * Kfc];
__device__ __nv_bfloat16 g_W1H[2L * G4 * Kfc];   // gate-interleaved [d][n][k]
__device__ __nv_bfloat16 g_W1L[2L * G4 * Kfc];
__device__ __nv_bfloat16 g_WsH[2][2][G4][Hd];    // recurrent weights [lay][d][n][k]
__device__ __nv_bfloat16 g_WsL[2][2][G4][Hd];

__device__ __forceinline__ uint32_t smem_u32(const void* p) {
    uint32_t a;
    asm("{ .reg .u64 t; cvta.to.shared.u64 t, %1; cvt.u32.u64 %0, t; }"
        : "=r"(a) : "l"(p));
    return a;
}
#define LDSM4(r, addr) \
    asm volatile("ldmatrix.sync.aligned.m8n8.x4.shared.b16 {%0,%1,%2,%3}, [%4];" \
        : "=r"((r)[0]), "=r"((r)[1]), "=r"((r)[2]), "=r"((r)[3]) : "r"(addr))
#define MMA16816(c, a, b) \
    asm volatile("mma.sync.aligned.m16n8k16.row.col.f32.bf16.bf16.f32 " \
        "{%0,%1,%2,%3}, {%4,%5,%6,%7}, {%8,%9}, {%0,%1,%2,%3};" \
        : "+f"((c)[0]), "+f"((c)[1]), "+f"((c)[2]), "+f"((c)[3]) \
        : "r"((a)[0]), "r"((a)[1]), "r"((a)[2]), "r"((a)[3]), "r"((b)[0]), "r"((b)[1]))

// ---------------- weight packing (fp32 for xproj, biases) ----------------
__global__ void k_pack(const float* __restrict__ Wih0,
                       const float* __restrict__ bih0, const float* __restrict__ bhh0,
                       const float* __restrict__ bih1, const float* __restrict__ bhh1) {
    int region = blockIdx.y;
    long i = (long)blockIdx.x * blockDim.x + threadIdx.x;
    if (region == 0) {
        if (i >= 2L * Ed * G4) return;
        int d = (int)(i / (Ed * G4)); int rem = (int)(i % (Ed * G4));
        int k = rem / G4, n = rem % G4;
        int h = n >> 2, g = n & 3;
        g_WihP0[d][k][n] = Wih0[((long)d * G4 + g * Hd + h) * Ed + k];
    } else if (region == 1) {
        if (i >= 2L * G4) return;
        int d = (int)(i / G4); int n = (int)(i % G4);
        int h = n >> 2, g = n & 3;
        long j = (long)d * G4 + g * Hd + h;
        g_bP0[d][n] = bih0[j] + bhh0[j];
    } else {
        if (i >= 2L * G4) return;
        int d = (int)(i / G4); int n = (int)(i % G4);
        int h = n >> 2, g = n & 3;
        long j = (long)d * G4 + g * Hd + h;
        g_bP1[d][n] = bih1[j] + bhh1[j];
    }
}

// ---------------- bf16 hi/lo split packing for tensor-core GEMMs ----------------
__global__ void k_packbf(const float* __restrict__ Wfc, const float* __restrict__ Wih1,
                         const float* __restrict__ Whh0, const float* __restrict__ Whh1) {
    long i = (long)blockIdx.x * blockDim.x + threadIdx.x;
    if (blockIdx.y == 0) {
        if (i >= (long)Vd * Kfc) return;
        float x = Wfc[i];
        __nv_bfloat16 h = __float2bfloat16(x);
        g_WfcH[i] = h;
        g_WfcL[i] = __float2bfloat16(x - __bfloat162float(h));
    } else if (blockIdx.y == 1) {
        if (i >= 2L * G4 * Kfc) return;
        int d = (int)(i / (G4 * Kfc)); long rem = i % ((long)G4 * Kfc);
        int n = (int)(rem / Kfc), k = (int)(rem % Kfc);
        int h = n >> 2, g = n & 3;
        float x = Wih1[((long)d * G4 + g * Hd + h) * Kfc + k];
        __nv_bfloat16 hb = __float2bfloat16(x);
        g_W1H[i] = hb;
        g_W1L[i] = __float2bfloat16(x - __bfloat162float(hb));
    } else {
        if (i >= 2L * 2 * G4 * Hd) return;
        int lay = (int)(i / (2L * G4 * Hd));
        long rem = i % (2L * G4 * Hd);
        int d = (int)(rem / ((long)G4 * Hd));
        long r2 = rem % ((long)G4 * Hd);
        int n = (int)(r2 / Hd), k = (int)(r2 % Hd);
        int h = n >> 2, g = n & 3;
        const float* W = lay ? Whh1 : Whh0;
        float x = W[((long)d * G4 + g * Hd + h) * Hd + k];
        __nv_bfloat16 hb = __float2bfloat16(x);
        g_WsH[lay][d][n][k] = hb;
        g_WsL[lay][d][n][k] = __float2bfloat16(x - __bfloat162float(hb));
    }
}

// ---------------- initial states: bf16 hi/lo h0, fp32 c0 ----------------
__global__ void k_init(const float* __restrict__ img, const float* __restrict__ Wh,
                       const float* __restrict__ bh, const float* __restrict__ Wc,
                       const float* __restrict__ bc) {
    int i = blockIdx.x * blockDim.x + threadIdx.x;
    if (i >= 2 * Bd * Hd) return;
    int which = i / (Bd * Hd);
    int rem = i % (Bd * Hd);
    int b = rem / Hd, j = rem % Hd;
    const float* W = which ? Wc : Wh;
    const float* bias = which ? bc : bh;
    const float4* a4 = (const float4*)(img + (long)b * CNNd);
    const float4* w4 = (const float4*)(W + (long)j * CNNd);
    float acc = 0.f;
#pragma unroll 4
    for (int k = 0; k < CNNd / 4; k++) {
        float4 a = a4[k], w = w4[k];
        acc += a.x * w.x + a.y * w.y + a.z * w.z + a.w * w.w;
    }
    float v = fmaxf(acc + bias[j], 0.f);
    __nv_bfloat16 hv = __float2bfloat16(v);
    __nv_bfloat16 lv = __float2bfloat16(v - __bfloat162float(hv));
    for (int nc = 0; nc < NCd; nc++) {
        int row = nc * Bd + b;
        for (int l = 0; l < 2; l++)
            for (int d = 0; d < 2; d++) {
                if (which == 0) { g_hbH[0][l][d][row][j] = hv; g_hbL[0][l][d][row][j] = lv; }
                else            g_cS[l][d][row][j] = v;
            }
    }
}

// ---------------- layer0 input projections for all t ----------------
__global__ void k_xproj(const float* __restrict__ emb, const int* __restrict__ cap) {
    __shared__ float xs[32 * Ed];
    __shared__ int toks[32];
    int bm = blockIdx.x, bn = blockIdx.y, d = blockIdx.z;
    int tid = threadIdx.x;
    if (tid < 32) {
        int m = bm * 32 + tid;
        int t = m / Rd, r = m % Rd;
        int nc = r >> 5, b = r & 31;
        toks[tid] = cap[b * (NCd * Td) + nc * Td + t];
    }
    __syncthreads();
    for (int e = tid; e < 32 * Ed; e += 256) {
        int lr = e / Ed, k = e % Ed;
        xs[e] = emb[(long)toks[lr] * Ed + k];
    }
    __syncthreads();
    int tx = tid & 31, ty = tid >> 5;
    float acc[4][4];
#pragma unroll
    for (int a = 0; a < 4; a++)
#pragma unroll
        for (int c = 0; c < 4; c++) acc[a][c] = 0.f;
    int n0 = bn * 128;
    const float* Bp = &g_WihP0[d][0][0];
#pragma unroll 5
    for (int k = 0; k < Ed; k++) {
        float av[4], bv[4];
#pragma unroll
        for (int jr = 0; jr < 4; jr++) av[jr] = xs[(ty + jr * 8) * Ed + k];
#pragma unroll
        for (int jc = 0; jc < 4; jc++) bv[jc] = Bp[(long)k * G4 + n0 + tx + jc * 32];
#pragma unroll
        for (int jr = 0; jr < 4; jr++)
#pragma unroll
            for (int jc = 0; jc < 4; jc++) acc[jr][jc] += av[jr] * bv[jc];
    }
    int m0 = bm * 32;
#pragma unroll
    for (int jr = 0; jr < 4; jr++) {
        int m = m0 + ty + jr * 8;
        int t = m / Rd, r = m % Rd;
#pragma unroll
        for (int jc = 0; jc < 4; jc++) {
            int n = n0 + tx + jc * 32;
            g_X0[d][t][r][n] = acc[jr][jc] + g_bP0[d][n];
        }
    }
}

// =========================================================================
// bf16-split mma.sync GEMM (unchanged from R5).
// mode 0: out[M=3200][Vd] = packed @ Wfc^T + bfc   grid (25, 239, 1)
// mode 1: Z[d][t][r][:] = Y @ W1^T + bP1           grid (Mtiles, 16, 2)
// =========================================================================
__global__ void __launch_bounds__(256, 1)
k_mma(int mode, int w, const float* __restrict__ bfc, float* __restrict__ out) {
    extern __shared__ __align__(16) char dsm[];
    __nv_bfloat16* sA_h = (__nv_bfloat16*)dsm;
    __nv_bfloat16* sA_l = sA_h + 2 * 128 * PITCH;
    __nv_bfloat16* sB_h = sA_l + 2 * 128 * PITCH;
    __nv_bfloat16* sB_l = sB_h + 2 * 128 * PITCH;
    uint32_t uAh = smem_u32(sA_h), uAl = smem_u32(sA_l);
    uint32_t uBh = smem_u32(sB_h), uBl = smem_u32(sB_l);

    int tid = threadIdx.x;
    int lane = tid & 31, wid = tid >> 5;
    int wm = wid >> 1, wn = wid & 1;
    int m0 = blockIdx.x * 128, n0 = blockIdx.y * 128, dz = blockIdx.z;
    int Mtot = mode ? (w + 1) * Rd : Md;

    int sr = tid & 127, kh = tid >> 7;
    int k0 = kh * 16;

    int am = m0 + sr; if (am >= Mtot) am = Mtot - 1;
    int att = 0, arr = 0;
    const __nv_bfloat16 *aH0 = nullptr, *aL0 = nullptr;
    if (mode == 0) { aH0 = &g_packedH[am][0]; aL0 = &g_packedL[am][0]; }
    else { att = am / Rd; arr = am - att * Rd; }

    int bnr = n0 + sr;
    bool bvalid = mode ? true : (bnr < Vd);
    const __nv_bfloat16* BH = mode ? g_W1H : g_WfcH;
    const __nv_bfloat16* BL = mode ? g_W1L : g_WfcL;
    long boff = mode ? ((long)dz * G4 + bnr) * Kfc : (long)bnr * Kfc;

    float c[2][8][4];
#pragma unroll
    for (int mt = 0; mt < 2; mt++)
#pragma unroll
        for (int nt = 0; nt < 8; nt++)
#pragma unroll
            for (int q = 0; q < 4; q++) c[mt][nt][q] = 0.f;

    uint4 vA[4], vB[4];

    auto LOAD = [&](int kc) {
        int kb = kc * 32 + k0;
        if (mode == 0) {
            vA[0] = *(const uint4*)(aH0 + kb);
            vA[1] = *(const uint4*)(aH0 + kb + 8);
            vA[2] = *(const uint4*)(aL0 + kb);
            vA[3] = *(const uint4*)(aL0 + kb + 8);
        } else {
#pragma unroll
            for (int q = 0; q < 2; q++) {
                int kg = kb + q * 8;
                const __nv_bfloat16* pH = (kg < Hd) ? &g_hsH[0][att][arr][kg]
                                                    : &g_hsH[1][w - att][arr][kg - Hd];
                const __nv_bfloat16* pL = (kg < Hd) ? &g_hsL[0][att][arr][kg]
                                                    : &g_hsL[1][w - att][arr][kg - Hd];
                vA[q] = *(const uint4*)pH;
                vA[2 + q] = *(const uint4*)pL;
            }
        }
        if (bvalid) {
            vB[0] = *(const uint4*)(BH + boff + kb);
            vB[1] = *(const uint4*)(BH + boff + kb + 8);
            vB[2] = *(const uint4*)(BL + boff + kb);
            vB[3] = *(const uint4*)(BL + boff + kb + 8);
        } else {
            uint4 z = make_uint4(0, 0, 0, 0);
            vB[0] = z; vB[1] = z; vB[2] = z; vB[3] = z;
        }
    };
    auto STORE = [&](int buf) {
        int base = buf * 128 * PITCH + sr * PITCH + k0;
        *(uint4*)&sA_h[base] = vA[0]; *(uint4*)&sA_h[base + 8] = vA[1];
        *(uint4*)&sA_l[base] = vA[2]; *(uint4*)&sA_l[base + 8] = vA[3];
        *(uint4*)&sB_h[base] = vB[0]; *(uint4*)&sB_h[base + 8] = vB[1];
        *(uint4*)&sB_l[base] = vB[2]; *(uint4*)&sB_l[base + 8] = vB[3];
    };
    auto COMPUTE = [&](int buf) {
        uint32_t bo = (uint32_t)buf * 128 * PITCH * 2;
#pragma unroll
        for (int k16 = 0; k16 < 2; k16++) {
            int ar = lane & 15;
            int acs = k16 * 16 + ((lane >> 4) << 3);
            uint32_t ah[2][4], al[2][4];
#pragma unroll
            for (int mt = 0; mt < 2; mt++) {
                uint32_t off = bo + (uint32_t)((wm * 32 + mt * 16 + ar) * PITCH + acs) * 2;
                LDSM4(ah[mt], uAh + off);
                LDSM4(al[mt], uAl + off);
            }
            int br = (lane & 7) + ((lane >> 4) << 3);
            int bcs = k16 * 16 + (((lane >> 3) & 1) << 3);
            uint32_t bh[8][2], bl[8][2];
#pragma unroll
            for (int ntp = 0; ntp < 4; ntp++) {
                uint32_t off = bo + (uint32_t)((wn * 64 + ntp * 16 + br) * PITCH + bcs) * 2;
                uint32_t r4[4];
                LDSM4(r4, uBh + off);
                bh[ntp * 2][0] = r4[0]; bh[ntp * 2][1] = r4[1];
                bh[ntp * 2 + 1][0] = r4[2]; bh[ntp * 2 + 1][1] = r4[3];
                LDSM4(r4, uBl + off);
                bl[ntp * 2][0] = r4[0]; bl[ntp * 2][1] = r4[1];
                bl[ntp * 2 + 1][0] = r4[2]; bl[ntp * 2 + 1][1] = r4[3];
            }
#pragma unroll
            for (int mt = 0; mt < 2; mt++)
#pragma unroll
                for (int nt = 0; nt < 8; nt++) {
                    MMA16816(c[mt][nt], ah[mt], bh[nt]);
                    MMA16816(c[mt][nt], ah[mt], bl[nt]);
                    MMA16816(c[mt][nt], al[mt], bh[nt]);
                }
        }
    };

    LOAD(0); STORE(0);
    __syncthreads();
    for (int kc = 0; kc < 32; kc++) {
        int buf = kc & 1;
        if (kc < 31) LOAD(kc + 1);
        COMPUTE(buf);
        if (kc < 31) STORE(buf ^ 1);
        __syncthreads();
    }

    int qrow = lane >> 2, qcol = (lane & 3) * 2;
#pragma unroll
    for (int mt = 0; mt < 2; mt++) {
#pragma unroll
        for (int nt = 0; nt < 8; nt++) {
            int n = n0 + wn * 64 + nt * 8 + qcol;
            int mA = m0 + wm * 32 + mt * 16 + qrow;
            if (mode == 0) {
                if (n < Vd) {
                    float2 bb = *(const float2*)&bfc[n];
                    float2 o0 = make_float2(c[mt][nt][0] + bb.x, c[mt][nt][1] + bb.y);
                    float2 o1 = make_float2(c[mt][nt][2] + bb.x, c[mt][nt][3] + bb.y);
                    *(float2*)&out[(long)mA * Vd + n] = o0;
                    *(float2*)&out[(long)(mA + 8) * Vd + n] = o1;
                }
            } else {
                float2 bb = *(const float2*)&g_bP1[dz][n];
                if (mA < Mtot) {
                    int t = mA / Rd, rr = mA - t * Rd;
                    *(float2*)&g_Z[dz][t][rr][n] =
                        make_float2(c[mt][nt][0] + bb.x, c[mt][nt][1] + bb.y);
                }
                if (mA + 8 < Mtot) {
                    int t = (mA + 8) / Rd, rr = (mA + 8) - t * Rd;
                    *(float2*)&g_Z[dz][t][rr][n] =
                        make_float2(c[mt][nt][2] + bb.x, c[mt][nt][3] + bb.y);
                }
            }
        }
    }
}

// =========================================================================
// mma.sync recurrent LSTM step with fused cell epilogue.
// grid (32, 4): blockIdx.x = n-tile (64 gates), blockIdx.y = dir + 2*lay.
// block 320 (10 warps, warp grid 5m x 2n, warp tile 32x32).
// gates = X + h @ Whh^T via 3-term bf16 split; cell in fragment epilogue.
// =========================================================================
__global__ void __launch_bounds__(320, 1)
k_stepm(int p0, int s0, int w0, int act0, int p1, int s1, int w1, int act1) {
    extern __shared__ __align__(16) char dsm[];
    __nv_bfloat16* sA_h = (__nv_bfloat16*)dsm;           // [2][160*PITCH]
    __nv_bfloat16* sA_l = sA_h + 2 * 160 * PITCH;
    __nv_bfloat16* sB_h = sA_l + 2 * 160 * PITCH;        // [2][64*PITCH]
    __nv_bfloat16* sB_l = sB_h + 2 * 64 * PITCH;
    uint32_t uAh = smem_u32(sA_h), uAl = smem_u32(sA_l);
    uint32_t uBh = smem_u32(sB_h), uBl = smem_u32(sB_l);

    int z = blockIdx.y;
    int lay = z >> 1, d = z & 1;
    int act = lay ? act1 : act0;
    if (!act) return;
    int p = lay ? p1 : p0;
    int s = lay ? s1 : s0;
    int w = lay ? w1 : w0;

    int tid = threadIdx.x;
    int lane = tid & 31, wid = tid >> 5;
    int wm = wid >> 1, wn = wid & 1;       // 5(m) x 2(n)
    int n0 = blockIdx.x * 64;

    const __nv_bfloat16* hH = &g_hbH[p][lay][d][0][0];
    const __nv_bfloat16* hL = &g_hbL[p][lay][d][0][0];
    __nv_bfloat16* hoH = &g_hbH[p ^ 1][lay][d][0][0];
    __nv_bfloat16* hoL = &g_hbL[p ^ 1][lay][d][0][0];
    float* cstp = &g_cS[lay][d][0][0];
    int xidx = d ? (w - s) : s;
    const float* Xp = lay ? &g_Z[d][xidx][0][0] : &g_X0[d][xidx][0][0];
    const __nv_bfloat16* BH = &g_WsH[lay][d][0][0];
    const __nv_bfloat16* BL = &g_WsL[lay][d][0][0];

    // staging coords
    int arow = (tid >= 160) ? tid - 160 : tid;   // 0..159
    int ahalf = (tid >= 160) ? 1 : 0;
    int ak0 = ahalf * 16;
    int brow = tid >> 1, bk0 = (tid & 1) * 16;   // tid<128

    float c[2][4][4];
#pragma unroll
    for (int mt = 0; mt < 2; mt++)
#pragma unroll
        for (int nt = 0; nt < 4; nt++)
#pragma unroll
            for (int q = 0; q < 4; q++) c[mt][nt][q] = 0.f;

    uint4 vA[4], vB[4];

    auto LOAD = [&](int kc) {
        int kb = kc * 32;
        int ka = kb + ak0;
        vA[0] = *(const uint4*)(hH + arow * Hd + ka);
        vA[1] = *(const uint4*)(hH + arow * Hd + ka + 8);
        vA[2] = *(const uint4*)(hL + arow * Hd + ka);
        vA[3] = *(const uint4*)(hL + arow * Hd + ka + 8);
        if (tid < 128) {
            long bo = (long)(n0 + brow) * Hd + kb + bk0;
            vB[0] = *(const uint4*)(BH + bo);
            vB[1] = *(const uint4*)(BH + bo + 8);
            vB[2] = *(const uint4*)(BL + bo);
            vB[3] = *(const uint4*)(BL + bo + 8);
        }
    };
    auto STORE = [&](int buf) {
        int sa = buf * 160 * PITCH + arow * PITCH + ak0;
        *(uint4*)&sA_h[sa] = vA[0]; *(uint4*)&sA_h[sa + 8] = vA[1];
        *(uint4*)&sA_l[sa] = vA[2]; *(uint4*)&sA_l[sa + 8] = vA[3];
        if (tid < 128) {
            int sbb = buf * 64 * PITCH + brow * PITCH + bk0;
            *(uint4*)&sB_h[sbb] = vB[0]; *(uint4*)&sB_h[sbb + 8] = vB[1];
            *(uint4*)&sB_l[sbb] = vB[2]; *(uint4*)&sB_l[sbb + 8] = vB[3];
        }
    };
    auto COMPUTE = [&](int buf) {
        uint32_t boA = (uint32_t)buf * 160 * PITCH * 2;
        uint32_t boB = (uint32_t)buf * 64 * PITCH * 2;
#pragma unroll
        for (int k16 = 0; k16 < 2; k16++) {
            int ar = lane & 15;
            int acs = k16 * 16 + ((lane >> 4) << 3);
            uint32_t ah[2][4], al[2][4];
#pragma unroll
            for (int mt = 0; mt < 2; mt++) {
                uint32_t off = boA + (uint32_t)((wm * 32 + mt * 16 + ar) * PITCH + acs) * 2;
                LDSM4(ah[mt], uAh + off);
                LDSM4(al[mt], uAl + off);
            }
            int br = (lane & 7) + ((lane >> 4) << 3);
            int bcs = k16 * 16 + (((lane >> 3) & 1) << 3);
            uint32_t bh[4][2], bl[4][2];
#pragma unroll
            for (int ntp = 0; ntp < 2; ntp++) {
                uint32_t off = boB + (uint32_t)((wn * 32 + ntp * 16 + br) * PITCH + bcs) * 2;
                uint32_t r4[4];
                LDSM4(r4, uBh + off);
                bh[ntp * 2][0] = r4[0]; bh[ntp * 2][1] = r4[1];
                bh[ntp * 2 + 1][0] = r4[2]; bh[ntp * 2 + 1][1] = r4[3];
                LDSM4(r4, uBl + off);
                bl[ntp * 2][0] = r4[0]; bl[ntp * 2][1] = r4[1];
                bl[ntp * 2 + 1][0] = r4[2]; bl[ntp * 2 + 1][1] = r4[3];
            }
#pragma unroll
            for (int mt = 0; mt < 2; mt++)
#pragma unroll
                for (int nt = 0; nt < 4; nt++) {
                    MMA16816(c[mt][nt], ah[mt], bh[nt]);
                    MMA16816(c[mt][nt], ah[mt], bl[nt]);
                    MMA16816(c[mt][nt], al[mt], bh[nt]);
                }
        }
    };

    LOAD(0); STORE(0);
    __syncthreads();
    for (int kc = 0; kc < 16; kc++) {
        int buf = kc & 1;
        if (kc < 15) LOAD(kc + 1);
        COMPUTE(buf);
        if (kc < 15) STORE(buf ^ 1);
        __syncthreads();
    }

    // ---- fused LSTM cell epilogue ----
    // fragment (mt,nt): rows wm*32+mt*16+qrow (+8), cols nbase+quad*2, +1
    // quad 0: (i,f) of h0 | quad 1: (g,o) of h0 | quad 2: (i,f) of h1 | quad 3: (g,o) of h1
    int qrow = lane >> 2, quad = lane & 3;
    bool isIF = (quad & 1) == 0;
#pragma unroll
    for (int mt = 0; mt < 2; mt++) {
#pragma unroll
        for (int nt = 0; nt < 4; nt++) {
            int nbase = n0 + wn * 32 + nt * 8;
            int n = nbase + quad * 2;
            int r1 = wm * 32 + mt * 16 + qrow;
            int r2 = r1 + 8;
            float2 x1 = *(const float2*)&Xp[(long)r1 * G4 + n];
            float2 x2 = *(const float2*)&Xp[(long)r2 * G4 + n];
            float a0 = c[mt][nt][0] + x1.x;
            float a1 = c[mt][nt][1] + x1.y;
            float a2 = c[mt][nt][2] + x2.x;
            float a3 = c[mt][nt][3] + x2.y;
            float b0 = __shfl_xor_sync(0xffffffffu, a0, 1);
            float b1 = __shfl_xor_sync(0xffffffffu, a1, 1);
            float b2 = __shfl_xor_sync(0xffffffffu, a2, 1);
            float b3 = __shfl_xor_sync(0xffffffffu, a3, 1);
            if (isIF) {
                int hh = (nbase >> 2) + (quad >> 1);
#pragma unroll
                for (int rr = 0; rr < 2; rr++) {
                    int row = rr ? r2 : r1;
                    float gi = rr ? a2 : a0;
                    float gf = rr ? a3 : a1;
                    float gg = rr ? b2 : b0;
                    float go = rr ? b3 : b1;
                    float si = 1.f / (1.f + expf(-gi));
                    float sf = 1.f / (1.f + expf(-gf));
                    float so = 1.f / (1.f + expf(-go));
                    float tg = tanhf(gg);
                    float cc = sf * cstp[row * Hd + hh] + si * tg;
                    float h = so * tanhf(cc);
                    cstp[row * Hd + hh] = cc;
                    __nv_bfloat16 hb = __float2bfloat16(h);
                    __nv_bfloat16 lb = __float2bfloat16(h - __bfloat162float(hb));
                    hoH[row * Hd + hh] = hb;
                    hoL[row * Hd + hh] = lb;
                    if (lay == 0) {
                        g_hsH[d][s][row][hh] = hb;
                        g_hsL[d][s][row][hh] = lb;
                    }
                }
            }
        }
    }
}

// ---------------- pack final layer1 states (copy bf16 hi/lo) ----------------
__global__ void k_packst(int w, int pb) {
    int i = blockIdx.x * blockDim.x + threadIdx.x;
    if (i >= Rd * 2 * Hd) return;
    int r = i / (2 * Hd), k = i % (2 * Hd);
    int nc = r >> 5, b = r & 31;
    __nv_bfloat16 hv, lv;
    if (k < Hd) { hv = g_hbH[pb][1][1][r][k]; lv = g_hbL[pb][1][1][r][k]; }
    else        { hv = g_hbH[pb][1][0][r][k - Hd]; lv = g_hbL[pb][1][0][r][k - Hd]; }
    int m = (nc * Td + w) * Bd + b;
    g_packedH[m][k] = hv;
    g_packedL[m][k] = lv;
}

// ---------------- host orchestration ----------------
#define MMA_SMEM  (8 * 128 * PITCH * 2)                       // 81920 bytes
#define STEP_SMEM ((2 * 160 * PITCH * 2 + 2 * 64 * PITCH * 2) * 2)  // 71680 bytes

extern "C" void kernel_launch(void* const* d_in, const int* in_sizes, int n_in,
                              void* d_out, int out_size) {
    const float* img  = (const float*)d_in[0];
    const int*   cap  = (const int*)d_in[1];
    const float* emb  = (const float*)d_in[2];
    const float* Wh   = (const float*)d_in[3];
    const float* bh   = (const float*)d_in[4];
    const float* Wc   = (const float*)d_in[5];
    const float* bc   = (const float*)d_in[6];
    const float* Wih0 = (const float*)d_in[7];
    const float* Whh0 = (const float*)d_in[8];
    const float* bih0 = (const float*)d_in[9];
    const float* bhh0 = (const float*)d_in[10];
    const float* Wih1 = (const float*)d_in[11];
    const float* Whh1 = (const float*)d_in[12];
    const float* bih1 = (const float*)d_in[13];
    const float* bhh1 = (const float*)d_in[14];
    const float* Wfc  = (const float*)d_in[15];
    const float* bfc  = (const float*)d_in[16];
    float* out = (float*)d_out;

    cudaFuncSetAttribute(k_mma, cudaFuncAttributeMaxDynamicSharedMemorySize, MMA_SMEM);
    cudaFuncSetAttribute(k_stepm, cudaFuncAttributeMaxDynamicSharedMemorySize, STEP_SMEM);

    k_pack<<<dim3(4000, 3), 256>>>(Wih0, bih0, bhh0, bih1, bhh1);
    k_packbf<<<dim3(122088, 3), 256>>>(Wfc, Wih1, Whh0, Whh1);
    k_init<<<(2 * Bd * Hd + 255) / 256, 256>>>(img, Wh, bh, Wc, bc);
    k_xproj<<<dim3(100, 16, 2), 256>>>(emb, cap);

    int p0 = 0, p1 = 0;
    // prelude: layer0 of word 0 (single step), then Z(0)
    k_stepm<<<dim3(32, 4), 320, STEP_SMEM>>>(p0, 0, 0, 1, p1, 0, 0, 0);
    p0 ^= 1;
    k_mma<<<dim3(2, 16, 2), 256, MMA_SMEM>>>(1, 0, nullptr, nullptr);

    for (int w = 0; w < Td; w++) {
        int s0max = (w + 1 < Td) ? (w + 1) : -1;   // layer0 word w+1 steps
        int s1max = w;                              // layer1 word w steps
        int smax = s0max > s1max ? s0max : s1max;
        for (int s = 0; s <= smax; s++) {
            int a0 = (s <= s0max) ? 1 : 0;
            int a1 = (s <= s1max) ? 1 : 0;
            k_stepm<<<dim3(32, 4), 320, STEP_SMEM>>>(p0, s, w + 1, a0, p1, s, w, a1);
            if (a0) p0 ^= 1;
            if (a1) p1 ^= 1;
        }
        k_packst<<<(Rd * 2 * Hd + 255) / 256, 256>>>(w, p1);
        if (w + 1 < Td) {
            int Mt = ((w + 2) * Rd + 127) / 128;
            k_mma<<<dim3(Mt, 16, 2), 256, MMA_SMEM>>>(1, w + 1, nullptr, nullptr);
        }
    }
    k_mma<<<dim3(25, 239, 1), 256, MMA_SMEM>>>(0, 0, bfc, out);
}